// round 1
// baseline (speedup 1.0000x reference)
#include <cuda_runtime.h>

// Problem constants (from reference): E=8, N=512, P=512, F=100, B=128
#define B_TRIALS 128
#define F_BINS   100
#define N_IN     512
#define H_MID    1024
#define P_OUT    512

// Scratch for the softsign activation: [B, F, H] fp32 = 52.4 MB (device global,
// no allocation — per harness rules).
__device__ float g_act[(size_t)B_TRIALS * F_BINS * H_MID];

// ---- packed f32x2 helpers (Blackwell sm_103a) ----
__device__ __forceinline__ unsigned long long pack2(float x) {
    unsigned long long r;
    asm("mov.b64 %0, {%1, %1};" : "=l"(r) : "f"(x));
    return r;
}
__device__ __forceinline__ void ffma2(unsigned long long& c,
                                      unsigned long long a,
                                      unsigned long long b) {
    asm("fma.rn.f32x2 %0, %1, %2, %0;" : "+l"(c) : "l"(a), "l"(b));
}
__device__ __forceinline__ void unpack2(unsigned long long v, float& lo, float& hi) {
    asm("mov.b64 {%0, %1}, %2;" : "=f"(lo), "=f"(hi) : "l"(v));
}

// Grouped per-sample GEMM: out[sample] = act( A[sample] @ W[eid[sample]] + bias[eid[sample]] )
//   A:    [B, F, K]     row-major (per-sample slab)
//   W:    [E, K, NOUT]  row-major (per-expert slab)
//   bias: [E, NOUT]
//   out:  [B, F, NOUT]
// Tile: BM=128 (covers F=100 with padding), BN=128, BK=8. 256 threads, 8x8 microtile.
// Accumulation in packed f32x2 pairs along the N dimension.
template <bool SOFTSIGN>
__global__ __launch_bounds__(256, 2)
void grouped_gemm(const float* __restrict__ A,
                  const float* __restrict__ W,
                  const float* __restrict__ bias,
                  const int*  __restrict__ eid,
                  float* __restrict__ out,
                  int K, int NOUT)
{
    const int sample = blockIdx.y;
    const int n0     = blockIdx.x * 128;
    const int e      = eid[sample];
    const int tid    = threadIdx.x;
    const int tm     = tid >> 4;   // 0..15
    const int tn     = tid & 15;   // 0..15

    __shared__ float As[2][8][128];  // [buf][k][m]  (A transposed)
    __shared__ float Bs[2][8][128];  // [buf][k][n]

    const float* Ap = A + (size_t)sample * F_BINS * K;
    const float* Wp = W + (size_t)e * K * NOUT + n0;

    // global-load assignments (one float4 per thread per tile)
    const int arow = tid >> 1;        // 0..127
    const int acol = (tid & 1) * 4;   // 0 or 4 (within BK=8)
    const int brow = tid >> 5;        // 0..7
    const int bcol = (tid & 31) * 4;  // 0..124

    unsigned long long acc[8][4];
#pragma unroll
    for (int i = 0; i < 8; i++)
#pragma unroll
        for (int j = 0; j < 4; j++) acc[i][j] = 0ull;

    const int ksteps = K >> 3;

    float4 aReg, bReg;
    // prologue: stage 0
    if (arow < F_BINS)
        aReg = *reinterpret_cast<const float4*>(Ap + (size_t)arow * K + acol);
    else
        aReg = make_float4(0.f, 0.f, 0.f, 0.f);
    bReg = *reinterpret_cast<const float4*>(Wp + (size_t)brow * NOUT + bcol);

    As[0][acol + 0][arow] = aReg.x;
    As[0][acol + 1][arow] = aReg.y;
    As[0][acol + 2][arow] = aReg.z;
    As[0][acol + 3][arow] = aReg.w;
    *reinterpret_cast<float4*>(&Bs[0][brow][bcol]) = bReg;
    __syncthreads();

    for (int kt = 0; kt < ksteps; kt++) {
        const int buf = kt & 1;
        const int nxt = buf ^ 1;

        // prefetch next tile global -> regs (overlaps with compute)
        const bool has_next = (kt + 1 < ksteps);
        if (has_next) {
            const int k0 = (kt + 1) << 3;
            if (arow < F_BINS)
                aReg = *reinterpret_cast<const float4*>(Ap + (size_t)arow * K + k0 + acol);
            else
                aReg = make_float4(0.f, 0.f, 0.f, 0.f);
            bReg = *reinterpret_cast<const float4*>(Wp + (size_t)(k0 + brow) * NOUT + bcol);
        }

        // compute on current buffer
#pragma unroll
        for (int kk = 0; kk < 8; kk++) {
            const float4 a0 = *reinterpret_cast<const float4*>(&As[buf][kk][tm * 8]);
            const float4 a1 = *reinterpret_cast<const float4*>(&As[buf][kk][tm * 8 + 4]);
            const unsigned long long* bsrc =
                reinterpret_cast<const unsigned long long*>(&Bs[buf][kk][tn * 8]);
            unsigned long long b0 = bsrc[0], b1 = bsrc[1], b2 = bsrc[2], b3 = bsrc[3];

            unsigned long long pa[8];
            pa[0] = pack2(a0.x); pa[1] = pack2(a0.y);
            pa[2] = pack2(a0.z); pa[3] = pack2(a0.w);
            pa[4] = pack2(a1.x); pa[5] = pack2(a1.y);
            pa[6] = pack2(a1.z); pa[7] = pack2(a1.w);

#pragma unroll
            for (int i = 0; i < 8; i++) {
                ffma2(acc[i][0], pa[i], b0);
                ffma2(acc[i][1], pa[i], b1);
                ffma2(acc[i][2], pa[i], b2);
                ffma2(acc[i][3], pa[i], b3);
            }
        }

        // store prefetched tile into the other buffer
        if (has_next) {
            As[nxt][acol + 0][arow] = aReg.x;
            As[nxt][acol + 1][arow] = aReg.y;
            As[nxt][acol + 2][arow] = aReg.z;
            As[nxt][acol + 3][arow] = aReg.w;
            *reinterpret_cast<float4*>(&Bs[nxt][brow][bcol]) = bReg;
        }
        __syncthreads();
    }

    // ---- epilogue: bias (+ softsign) and store ----
    const int ocol0 = n0 + tn * 8;
    const float2* bp = reinterpret_cast<const float2*>(bias + (size_t)e * NOUT + ocol0);
    float2 bv[4];
#pragma unroll
    for (int j = 0; j < 4; j++) bv[j] = bp[j];

    float* outp = out + (size_t)sample * F_BINS * NOUT;
#pragma unroll
    for (int i = 0; i < 8; i++) {
        const int row = tm * 8 + i;
        if (row < F_BINS) {
#pragma unroll
            for (int j = 0; j < 4; j++) {
                float lo, hi;
                unpack2(acc[i][j], lo, hi);
                float sx = lo + bv[j].x;
                float sy = hi + bv[j].y;
                if (SOFTSIGN) {
                    sx = sx / (1.0f + fabsf(sx));
                    sy = sy / (1.0f + fabsf(sy));
                }
                float2 v = make_float2(sx, sy);
                *reinterpret_cast<float2*>(outp + (size_t)row * NOUT + ocol0 + 2 * j) = v;
            }
        }
    }
}

extern "C" void kernel_launch(void* const* d_in, const int* in_sizes, int n_in,
                              void* d_out, int out_size)
{
    const float* x   = (const float*)d_in[0];
    const int*   eid = (const int*)d_in[1];
    const float* W1  = (const float*)d_in[2];
    const float* b1  = (const float*)d_in[3];
    const float* W2  = (const float*)d_in[4];
    const float* b2  = (const float*)d_in[5];
    float* out = (float*)d_out;

    float* act = nullptr;
    cudaGetSymbolAddress((void**)&act, g_act);

    dim3 blk(256);
    // GEMM1 + bias + softsign -> g_act : [B,F,H]
    grouped_gemm<true ><<<dim3(H_MID / 128, B_TRIALS), blk>>>(x,   W1, b1, eid, act, N_IN,  H_MID);
    // GEMM2 + bias -> out : [B,F,P]
    grouped_gemm<false><<<dim3(P_OUT / 128, B_TRIALS), blk>>>(act, W2, b2, eid, out, H_MID, P_OUT);
}

// round 3
// speedup vs baseline: 2.1631x; 2.1631x over previous
#include <cuda_runtime.h>
#include <cuda_bf16.h>
#include <cstdint>

// Problem constants: E=8, N=512(K1), H=1024, P=512, F=100, B=128
#define E_NUM    8
#define B_TRIALS 128
#define F_BINS   100
#define N_IN     512
#define H_MID    1024
#define P_OUT    512

// ---------------- device scratch (no allocation allowed) ----------------
__device__ __nv_bfloat16 g_xh[(size_t)B_TRIALS * F_BINS * N_IN];
__device__ __nv_bfloat16 g_xl[(size_t)B_TRIALS * F_BINS * N_IN];
__device__ __nv_bfloat16 g_w1h[(size_t)E_NUM * H_MID * N_IN];   // [E, N(out), K] K-major
__device__ __nv_bfloat16 g_w1l[(size_t)E_NUM * H_MID * N_IN];
__device__ __nv_bfloat16 g_w2h[(size_t)E_NUM * P_OUT * H_MID];
__device__ __nv_bfloat16 g_w2l[(size_t)E_NUM * P_OUT * H_MID];
__device__ __nv_bfloat16 g_ah[(size_t)B_TRIALS * 128 * H_MID];  // act hi, rows padded to 128
__device__ __nv_bfloat16 g_al[(size_t)B_TRIALS * 128 * H_MID];  // act lo

// ---------------- low-level helpers (compute_103-baseline PTX only) ----------------
__device__ __forceinline__ uint32_t smem_to_u32(const void* p) {
    uint32_t a;
    asm("{ .reg .u64 t; cvta.to.shared.u64 t, %1; cvt.u32.u64 %0, t; }"
        : "=r"(a) : "l"(p));
    return a;
}
#define SWZ128(o) ((o) ^ (((o) >> 3) & 0x70))

__device__ __forceinline__ void cp16(uint32_t dst, const void* src, uint32_t src_sz) {
    asm volatile("cp.async.cg.shared.global [%0], [%1], 16, %2;"
                 :: "r"(dst), "l"(src), "r"(src_sz) : "memory");
}
#define CP_COMMIT() asm volatile("cp.async.commit_group;" ::: "memory")
#define CP_WAIT1()  asm volatile("cp.async.wait_group 1;" ::: "memory")

__device__ __forceinline__ void ldsm4(uint32_t* r, uint32_t addr) {
    asm volatile("ldmatrix.sync.aligned.m8n8.x4.shared.b16 {%0,%1,%2,%3}, [%4];"
                 : "=r"(r[0]), "=r"(r[1]), "=r"(r[2]), "=r"(r[3]) : "r"(addr));
}
__device__ __forceinline__ void mma16816(float* c, const uint32_t* a,
                                         uint32_t b0, uint32_t b1) {
    asm volatile(
        "mma.sync.aligned.m16n8k16.row.col.f32.bf16.bf16.f32 "
        "{%0,%1,%2,%3}, {%4,%5,%6,%7}, {%8,%9}, {%0,%1,%2,%3};"
        : "+f"(c[0]), "+f"(c[1]), "+f"(c[2]), "+f"(c[3])
        : "r"(a[0]), "r"(a[1]), "r"(a[2]), "r"(a[3]), "r"(b0), "r"(b1));
}

// ---------------- conversion kernels ----------------
__global__ void convert_x_kernel(const float* __restrict__ x,
                                 __nv_bfloat16* __restrict__ xh,
                                 __nv_bfloat16* __restrict__ xl, int n4) {
    int i = blockIdx.x * blockDim.x + threadIdx.x;
    if (i >= n4) return;
    float4 v = reinterpret_cast<const float4*>(x)[i];
    float f[4] = {v.x, v.y, v.z, v.w};
    __nv_bfloat16 hb[4], lb[4];
#pragma unroll
    for (int j = 0; j < 4; j++) {
        hb[j] = __float2bfloat16(f[j]);
        lb[j] = __float2bfloat16(f[j] - __bfloat162float(hb[j]));
    }
    reinterpret_cast<uint2*>(xh)[i] = *reinterpret_cast<uint2*>(hb);
    reinterpret_cast<uint2*>(xl)[i] = *reinterpret_cast<uint2*>(lb);
}

// W [E,K,Nt] fp32 -> Wh/Wl [E,Nt,K] bf16 (transpose + hi/lo split)
__global__ void convert_w_kernel(const float* __restrict__ W,
                                 __nv_bfloat16* __restrict__ Wh,
                                 __nv_bfloat16* __restrict__ Wl, int K, int Nt) {
    __shared__ float t[32][33];
    int e  = blockIdx.z;
    int n0 = blockIdx.x * 32;
    int k0 = blockIdx.y * 32;
    const float* src = W + ((size_t)e * K + k0) * Nt + n0;
    t[threadIdx.y][threadIdx.x] = src[(size_t)threadIdx.y * Nt + threadIdx.x];
    __syncthreads();
    float v = t[threadIdx.x][threadIdx.y];  // = W[e][k0+tx][n0+ty]
    __nv_bfloat16 h = __float2bfloat16(v);
    __nv_bfloat16 l = __float2bfloat16(v - __bfloat162float(h));
    size_t dst = ((size_t)e * Nt + (n0 + threadIdx.y)) * K + k0 + threadIdx.x;
    Wh[dst] = h;
    Wl[dst] = l;
}

// ---------------- grouped bf16 hi/lo mma.sync GEMM ----------------
// CTA tile: M=128 x N=256, BK=64 bf16 (128B rows, SW128). 8 warps, warp tile 64x64.
// smem per stage: A_hi 16K | A_lo 16K | B_hi 32K | B_lo 32K = 96KB, double buffered.
#define OFF_AH   0
#define OFF_AL   16384
#define OFF_BH   32768
#define OFF_BL   65536
#define STAGE_SZ 98304
#define SMEM_DYN (2 * STAGE_SZ)

template <bool SOFTSIGN>
__global__ __launch_bounds__(256, 1)
void mma_gemm(const __nv_bfloat16* __restrict__ Ah, const __nv_bfloat16* __restrict__ Al,
              const __nv_bfloat16* __restrict__ Bh, const __nv_bfloat16* __restrict__ Bl,
              const float* __restrict__ bias, const int* __restrict__ eid,
              float* __restrict__ outF,
              __nv_bfloat16* __restrict__ outH, __nv_bfloat16* __restrict__ outL,
              int K, int Ntot, int a_rows, int a_stride)
{
    extern __shared__ __align__(1024) char smem[];
    const uint32_t sb = smem_to_u32(smem);
    const int tid    = threadIdx.x;
    const int wid    = tid >> 5;
    const int lid    = tid & 31;
    const int wm     = wid & 1;   // warp row (2)
    const int wn     = wid >> 1;  // warp col (4)
    const int sample = blockIdx.y;
    const int n0     = blockIdx.x * 256;
    const int e      = eid[sample];

    const __nv_bfloat16* aSrc[2] = {Ah, Al};
    const __nv_bfloat16* bSrc[2] = {Bh, Bl};

    const int nst = K >> 6;

    auto load_stage = [&](int s) {
        const int k0 = s << 6;
        const uint32_t tb = sb + (uint32_t)(s & 1) * STAGE_SZ;
        // A tiles hi+lo: 128 rows x 8 16B-chunks x 2 arrays = 2048 slots
#pragma unroll
        for (int it = 0; it < 8; it++) {
            int slot = it * 256 + tid;
            int arr  = slot >> 10;
            int idx  = slot & 1023;
            int r    = idx >> 3;
            int c    = idx & 7;
            int rs   = r < a_rows ? r : 0;
            const __nv_bfloat16* src =
                aSrc[arr] + ((size_t)sample * a_stride + rs) * K + k0 + c * 8;
            uint32_t dst = tb + (arr ? OFF_AL : OFF_AH) + SWZ128((uint32_t)(r * 128 + c * 16));
            cp16(dst, src, r < a_rows ? 16u : 0u);
        }
        // B tiles hi+lo: 256 rows x 8 chunks x 2 arrays = 4096 slots
#pragma unroll
        for (int it = 0; it < 16; it++) {
            int slot = it * 256 + tid;
            int arr  = slot >> 11;
            int idx  = slot & 2047;
            int r    = idx >> 3;
            int c    = idx & 7;
            const __nv_bfloat16* src =
                bSrc[arr] + ((size_t)e * Ntot + n0 + r) * K + k0 + c * 8;
            uint32_t dst = tb + (arr ? OFF_BL : OFF_BH) + SWZ128((uint32_t)(r * 128 + c * 16));
            cp16(dst, src, 16u);
        }
        CP_COMMIT();
    };

    float acc[4][8][4];
#pragma unroll
    for (int mt = 0; mt < 4; mt++)
#pragma unroll
        for (int nt = 0; nt < 8; nt++)
#pragma unroll
            for (int q = 0; q < 4; q++) acc[mt][nt][q] = 0.0f;

    load_stage(0);
    load_stage(1);

    for (int s = 0; s < nst; s++) {
        CP_WAIT1();
        __syncthreads();
        const uint32_t base = sb + (uint32_t)(s & 1) * STAGE_SZ;

#pragma unroll
        for (int kk = 0; kk < 4; kk++) {
            const uint32_t cb = (uint32_t)(kk * 32 + ((lid >> 4) << 4));
            uint32_t bh[16], blo[16];
#pragma unroll
            for (int np = 0; np < 4; np++) {
                const uint32_t off =
                    SWZ128((uint32_t)((wn * 64 + np * 16 + (lid & 15)) * 128) + cb);
                ldsm4(bh  + np * 4, base + OFF_BH + off);
                ldsm4(blo + np * 4, base + OFF_BL + off);
            }
#pragma unroll
            for (int mt = 0; mt < 4; mt++) {
                const uint32_t off =
                    SWZ128((uint32_t)((wm * 64 + mt * 16 + (lid & 15)) * 128) + cb);
                uint32_t ah[4], al[4];
                ldsm4(ah, base + OFF_AH + off);
                ldsm4(al, base + OFF_AL + off);
#pragma unroll
                for (int nt = 0; nt < 8; nt++) {
                    const int np = nt >> 1, q = nt & 1;
                    const uint32_t b0h = bh[np * 4 + q],  b1h = bh[np * 4 + 2 + q];
                    const uint32_t b0l = blo[np * 4 + q], b1l = blo[np * 4 + 2 + q];
                    mma16816(acc[mt][nt], ah, b0h, b1h);  // hi*hi
                    mma16816(acc[mt][nt], al, b0h, b1h);  // lo*hi
                    mma16816(acc[mt][nt], ah, b0l, b1l);  // hi*lo
                }
            }
        }
        __syncthreads();
        if (s + 2 < nst) load_stage(s + 2);
        else CP_COMMIT();  // keep commit-group count uniform
    }

    // ---------------- epilogue ----------------
    const int gq = lid >> 2;   // row-in-tile / 4
    const int rq = lid & 3;    // col pair index
    float2 bv[8];
#pragma unroll
    for (int nt = 0; nt < 8; nt++) {
        const int col = n0 + wn * 64 + nt * 8 + rq * 2;
        bv[nt] = *reinterpret_cast<const float2*>(bias + (size_t)e * Ntot + col);
    }

#pragma unroll
    for (int mt = 0; mt < 4; mt++) {
#pragma unroll
        for (int nt = 0; nt < 8; nt++) {
            const int row0 = wm * 64 + mt * 16 + gq;
            const int col  = n0 + wn * 64 + nt * 8 + rq * 2;
            float c0 = acc[mt][nt][0] + bv[nt].x;
            float c1 = acc[mt][nt][1] + bv[nt].y;
            float c2 = acc[mt][nt][2] + bv[nt].x;
            float c3 = acc[mt][nt][3] + bv[nt].y;
            if (SOFTSIGN) {
                c0 = c0 / (1.0f + fabsf(c0));
                c1 = c1 / (1.0f + fabsf(c1));
                c2 = c2 / (1.0f + fabsf(c2));
                c3 = c3 / (1.0f + fabsf(c3));
                __nv_bfloat16 h0 = __float2bfloat16(c0), h1 = __float2bfloat16(c1);
                __nv_bfloat16 h2 = __float2bfloat16(c2), h3 = __float2bfloat16(c3);
                __nv_bfloat16 l0 = __float2bfloat16(c0 - __bfloat162float(h0));
                __nv_bfloat16 l1 = __float2bfloat16(c1 - __bfloat162float(h1));
                __nv_bfloat16 l2 = __float2bfloat16(c2 - __bfloat162float(h2));
                __nv_bfloat16 l3 = __float2bfloat16(c3 - __bfloat162float(h3));
                size_t o0 = ((size_t)sample * 128 + row0) * Ntot + col;
                size_t o1 = ((size_t)sample * 128 + row0 + 8) * Ntot + col;
                *reinterpret_cast<__nv_bfloat162*>(outH + o0) = __nv_bfloat162(h0, h1);
                *reinterpret_cast<__nv_bfloat162*>(outH + o1) = __nv_bfloat162(h2, h3);
                *reinterpret_cast<__nv_bfloat162*>(outL + o0) = __nv_bfloat162(l0, l1);
                *reinterpret_cast<__nv_bfloat162*>(outL + o1) = __nv_bfloat162(l2, l3);
            } else {
                if (row0 < F_BINS) {
                    size_t o0 = ((size_t)sample * F_BINS + row0) * Ntot + col;
                    *reinterpret_cast<float2*>(outF + o0) = make_float2(c0, c1);
                }
                if (row0 + 8 < F_BINS) {
                    size_t o1 = ((size_t)sample * F_BINS + row0 + 8) * Ntot + col;
                    *reinterpret_cast<float2*>(outF + o1) = make_float2(c2, c3);
                }
            }
        }
    }
}

// ---------------- host launcher ----------------
extern "C" void kernel_launch(void* const* d_in, const int* in_sizes, int n_in,
                              void* d_out, int out_size)
{
    const float* x   = (const float*)d_in[0];
    const int*   eid = (const int*)d_in[1];
    const float* W1  = (const float*)d_in[2];
    const float* b1  = (const float*)d_in[3];
    const float* W2  = (const float*)d_in[4];
    const float* b2  = (const float*)d_in[5];
    float* out = (float*)d_out;

    __nv_bfloat16 *xh, *xl, *w1h, *w1l, *w2h, *w2l, *ah, *al;
    cudaGetSymbolAddress((void**)&xh,  g_xh);
    cudaGetSymbolAddress((void**)&xl,  g_xl);
    cudaGetSymbolAddress((void**)&w1h, g_w1h);
    cudaGetSymbolAddress((void**)&w1l, g_w1l);
    cudaGetSymbolAddress((void**)&w2h, g_w2h);
    cudaGetSymbolAddress((void**)&w2l, g_w2l);
    cudaGetSymbolAddress((void**)&ah,  g_ah);
    cudaGetSymbolAddress((void**)&al,  g_al);

    cudaFuncSetAttribute(mma_gemm<true>,
                         cudaFuncAttributeMaxDynamicSharedMemorySize, SMEM_DYN);
    cudaFuncSetAttribute(mma_gemm<false>,
                         cudaFuncAttributeMaxDynamicSharedMemorySize, SMEM_DYN);

    // 1) x -> bf16 hi/lo
    {
        int n4 = (B_TRIALS * F_BINS * N_IN) / 4;
        convert_x_kernel<<<(n4 + 255) / 256, 256>>>(x, xh, xl, n4);
    }
    // 2) weights: transpose + split
    {
        dim3 blk(32, 32);
        convert_w_kernel<<<dim3(H_MID / 32, N_IN / 32, E_NUM), blk>>>(W1, w1h, w1l, N_IN, H_MID);
        convert_w_kernel<<<dim3(P_OUT / 32, H_MID / 32, E_NUM), blk>>>(W2, w2h, w2l, H_MID, P_OUT);
    }
    // 3) GEMM1: x[B,100,512] @ W1[e] -> softsign -> act hi/lo [B,128,1024]
    mma_gemm<true><<<dim3(H_MID / 256, B_TRIALS), 256, SMEM_DYN>>>(
        xh, xl, w1h, w1l, b1, eid, nullptr, ah, al,
        /*K=*/N_IN, /*Ntot=*/H_MID, /*a_rows=*/F_BINS, /*a_stride=*/F_BINS);
    // 4) GEMM2: act [B,128,1024] @ W2[e] -> out fp32 [B,100,512]
    mma_gemm<false><<<dim3(P_OUT / 256, B_TRIALS), 256, SMEM_DYN>>>(
        ah, al, w2h, w2l, b2, eid, out, nullptr, nullptr,
        /*K=*/H_MID, /*Ntot=*/P_OUT, /*a_rows=*/128, /*a_stride=*/128);
}

// round 4
// speedup vs baseline: 2.2521x; 1.0412x over previous
#include <cuda_runtime.h>
#include <cuda_bf16.h>
#include <cstdint>

// Problem constants: E=8, N=512(K1), H=1024, P=512, F=100, B=128
#define E_NUM    8
#define B_TRIALS 128
#define F_BINS   100
#define N_IN     512
#define H_MID    1024
#define P_OUT    512
#define TOTAL_ROWS (B_TRIALS * F_BINS)   // 12800 packed rows
#define ACT_ROWS   13056                  // padded (12800 + 2*128)
#define MAXTILES   112

// ---------------- device scratch (no allocation allowed) ----------------
__device__ __nv_bfloat16 g_xh[(size_t)TOTAL_ROWS * N_IN];
__device__ __nv_bfloat16 g_xl[(size_t)TOTAL_ROWS * N_IN];
__device__ __nv_bfloat16 g_w1h[(size_t)E_NUM * H_MID * N_IN];   // [E, N(out), K] K-major
__device__ __nv_bfloat16 g_w1l[(size_t)E_NUM * H_MID * N_IN];
__device__ __nv_bfloat16 g_w2h[(size_t)E_NUM * P_OUT * H_MID];
__device__ __nv_bfloat16 g_w2l[(size_t)E_NUM * P_OUT * H_MID];
__device__ __nv_bfloat16 g_ah[(size_t)ACT_ROWS * H_MID];        // packed act hi
__device__ __nv_bfloat16 g_al[(size_t)ACT_ROWS * H_MID];        // packed act lo

// expert-sort metadata
__device__ int  g_order[B_TRIALS];
__device__ int  g_rowmap[TOTAL_ROWS];     // packed row -> source row (sample*100+f)
__device__ int4 g_tiles[MAXTILES];        // {expert, row0, rowend, 0}
__device__ int  g_ntiles;

// ---------------- low-level helpers (compute_103-baseline PTX only) ----------------
__device__ __forceinline__ uint32_t smem_to_u32(const void* p) {
    uint32_t a;
    asm("{ .reg .u64 t; cvta.to.shared.u64 t, %1; cvt.u32.u64 %0, t; }"
        : "=r"(a) : "l"(p));
    return a;
}
#define SWZ128(o) ((o) ^ (((o) >> 3) & 0x70))

__device__ __forceinline__ void cp16(uint32_t dst, const void* src, uint32_t src_sz) {
    asm volatile("cp.async.cg.shared.global [%0], [%1], 16, %2;"
                 :: "r"(dst), "l"(src), "r"(src_sz) : "memory");
}
#define CP_COMMIT() asm volatile("cp.async.commit_group;" ::: "memory")
#define CP_WAIT1()  asm volatile("cp.async.wait_group 1;" ::: "memory")

__device__ __forceinline__ void ldsm4(uint32_t* r, uint32_t addr) {
    asm volatile("ldmatrix.sync.aligned.m8n8.x4.shared.b16 {%0,%1,%2,%3}, [%4];"
                 : "=r"(r[0]), "=r"(r[1]), "=r"(r[2]), "=r"(r[3]) : "r"(addr));
}
__device__ __forceinline__ void mma16816(float* c, const uint32_t* a,
                                         uint32_t b0, uint32_t b1) {
    asm volatile(
        "mma.sync.aligned.m16n8k16.row.col.f32.bf16.bf16.f32 "
        "{%0,%1,%2,%3}, {%4,%5,%6,%7}, {%8,%9}, {%0,%1,%2,%3};"
        : "+f"(c[0]), "+f"(c[1]), "+f"(c[2]), "+f"(c[3])
        : "r"(a[0]), "r"(a[1]), "r"(a[2]), "r"(a[3]), "r"(b0), "r"(b1));
}

// ---------------- prep kernel: expert sort + tile table + rowmap ----------------
__global__ void prep_kernel(const int* __restrict__ eid) {
    __shared__ int cnt[E_NUM], off[E_NUM];
    const int tid = threadIdx.x;
    if (tid < E_NUM) cnt[tid] = 0;
    __syncthreads();
    if (tid < B_TRIALS) atomicAdd(&cnt[eid[tid]], 1);
    __syncthreads();
    if (tid == 0) {
        int o = 0;
        for (int g = 0; g < E_NUM; g++) { off[g] = o; o += cnt[g]; }
        int c[E_NUM];
        for (int g = 0; g < E_NUM; g++) c[g] = 0;
        for (int i = 0; i < B_TRIALS; i++) {
            int g = eid[i];
            g_order[off[g] + c[g]++] = i;
        }
        int t = 0;
        for (int g = 0; g < E_NUM; g++) {
            int r0 = off[g] * F_BINS;
            int r1 = (off[g] + cnt[g]) * F_BINS;
            for (int r = r0; r < r1; r += 128)
                g_tiles[t++] = make_int4(g, r, r1, 0);
        }
        g_ntiles = t;
        for (; t < MAXTILES; t++) g_tiles[t] = make_int4(0, 0, 0, 0);
    }
    __syncthreads();
    for (int j = tid; j < TOTAL_ROWS; j += blockDim.x)
        g_rowmap[j] = g_order[j / F_BINS] * F_BINS + (j % F_BINS);
}

// ---------------- conversion kernels ----------------
__global__ void convert_x_kernel(const float* __restrict__ x,
                                 __nv_bfloat16* __restrict__ xh,
                                 __nv_bfloat16* __restrict__ xl, int n4) {
    int i = blockIdx.x * blockDim.x + threadIdx.x;
    if (i >= n4) return;
    float4 v = reinterpret_cast<const float4*>(x)[i];
    float f[4] = {v.x, v.y, v.z, v.w};
    __nv_bfloat16 hb[4], lb[4];
#pragma unroll
    for (int j = 0; j < 4; j++) {
        hb[j] = __float2bfloat16(f[j]);
        lb[j] = __float2bfloat16(f[j] - __bfloat162float(hb[j]));
    }
    reinterpret_cast<uint2*>(xh)[i] = *reinterpret_cast<uint2*>(hb);
    reinterpret_cast<uint2*>(xl)[i] = *reinterpret_cast<uint2*>(lb);
}

// W [E,K,Nt] fp32 -> Wh/Wl [E,Nt,K] bf16 (transpose + hi/lo split)
__global__ void convert_w_kernel(const float* __restrict__ W,
                                 __nv_bfloat16* __restrict__ Wh,
                                 __nv_bfloat16* __restrict__ Wl, int K, int Nt) {
    __shared__ float t[32][33];
    int e  = blockIdx.z;
    int n0 = blockIdx.x * 32;
    int k0 = blockIdx.y * 32;
    const float* src = W + ((size_t)e * K + k0) * Nt + n0;
    t[threadIdx.y][threadIdx.x] = src[(size_t)threadIdx.y * Nt + threadIdx.x];
    __syncthreads();
    float v = t[threadIdx.x][threadIdx.y];  // = W[e][k0+tx][n0+ty]
    __nv_bfloat16 h = __float2bfloat16(v);
    __nv_bfloat16 l = __float2bfloat16(v - __bfloat162float(h));
    size_t dst = ((size_t)e * Nt + (n0 + threadIdx.y)) * K + k0 + threadIdx.x;
    Wh[dst] = h;
    Wl[dst] = l;
}

// ---------------- grouped bf16 hi/lo mma.sync GEMM (expert-packed M) ----------------
// CTA tile: M=128 x N=256, BK=64 bf16 (128B rows, SW128). 8 warps, warp tile 64x64.
// smem per stage: A_hi 16K | A_lo 16K | B_hi 32K | B_lo 32K = 96KB, double buffered.
#define OFF_AH   0
#define OFF_AL   16384
#define OFF_BH   32768
#define OFF_BL   65536
#define STAGE_SZ 98304
#define SMEM_DYN (2 * STAGE_SZ)

// SOFTSIGN=true: GEMM1 (A = x via rowmap gather, out = packed act hi/lo)
// SOFTSIGN=false: GEMM2 (A = packed act direct, out = scatter via rowmap)
template <bool SOFTSIGN>
__global__ __launch_bounds__(256, 1)
void mma_gemm(const __nv_bfloat16* __restrict__ Ah, const __nv_bfloat16* __restrict__ Al,
              const __nv_bfloat16* __restrict__ Bh, const __nv_bfloat16* __restrict__ Bl,
              const float* __restrict__ bias,
              float* __restrict__ outF,
              __nv_bfloat16* __restrict__ outH, __nv_bfloat16* __restrict__ outL,
              int K, int Ntot)
{
    if ((int)blockIdx.y >= g_ntiles) return;
    const int4 tt    = g_tiles[blockIdx.y];
    const int  e     = tt.x;
    const int  row0  = tt.y;
    const int  rowend= tt.z;

    extern __shared__ __align__(1024) char smem[];
    __shared__ int rm[128];
    const uint32_t sb = smem_to_u32(smem);
    const int tid    = threadIdx.x;
    const int wid    = tid >> 5;
    const int lid    = tid & 31;
    const int wm     = wid & 1;   // warp row (2)
    const int wn     = wid >> 1;  // warp col (4)
    const int n0     = blockIdx.x * 256;

    // rowmap slice for this tile (A gather in GEMM1, out scatter in GEMM2)
    if (tid < 128) {
        const int r = row0 + tid;
        rm[tid] = (r < rowend) ? g_rowmap[r] : -1;
    }
    __syncthreads();

    const __nv_bfloat16* aSrc[2] = {Ah, Al};
    const __nv_bfloat16* bSrc[2] = {Bh, Bl};
    const int nst = K >> 6;

    auto load_stage = [&](int s) {
        const int k0 = s << 6;
        const uint32_t tb = sb + (uint32_t)(s & 1) * STAGE_SZ;
        // A tiles hi+lo: 128 rows x 8 16B-chunks x 2 arrays = 2048 slots
#pragma unroll
        for (int it = 0; it < 8; it++) {
            int slot = it * 256 + tid;
            int arr  = slot >> 10;
            int idx  = slot & 1023;
            int r    = idx >> 3;
            int c    = idx & 7;
            const __nv_bfloat16* src;
            uint32_t sz;
            if (SOFTSIGN) {  // gather x rows through rowmap
                int sr = rm[r];
                src = aSrc[arr] + (size_t)(sr < 0 ? 0 : sr) * K + k0 + c * 8;
                sz  = (sr < 0) ? 0u : 16u;
            } else {         // packed act, direct
                src = aSrc[arr] + (size_t)(row0 + r) * K + k0 + c * 8;
                sz  = 16u;
            }
            uint32_t dst = tb + (arr ? OFF_AL : OFF_AH) + SWZ128((uint32_t)(r * 128 + c * 16));
            cp16(dst, src, sz);
        }
        // B tiles hi+lo: 256 rows x 8 chunks x 2 arrays = 4096 slots
#pragma unroll
        for (int it = 0; it < 16; it++) {
            int slot = it * 256 + tid;
            int arr  = slot >> 11;
            int idx  = slot & 2047;
            int r    = idx >> 3;
            int c    = idx & 7;
            const __nv_bfloat16* src =
                bSrc[arr] + ((size_t)e * Ntot + n0 + r) * K + k0 + c * 8;
            uint32_t dst = tb + (arr ? OFF_BL : OFF_BH) + SWZ128((uint32_t)(r * 128 + c * 16));
            cp16(dst, src, 16u);
        }
        CP_COMMIT();
    };

    float acc[4][8][4];
#pragma unroll
    for (int mt = 0; mt < 4; mt++)
#pragma unroll
        for (int nt = 0; nt < 8; nt++)
#pragma unroll
            for (int q = 0; q < 4; q++) acc[mt][nt][q] = 0.0f;

    load_stage(0);
    load_stage(1);

    for (int s = 0; s < nst; s++) {
        CP_WAIT1();
        __syncthreads();
        const uint32_t base = sb + (uint32_t)(s & 1) * STAGE_SZ;

#pragma unroll
        for (int kk = 0; kk < 4; kk++) {
            const uint32_t cb = (uint32_t)(kk * 32 + ((lid >> 4) << 4));
            uint32_t bh[16], blo[16];
#pragma unroll
            for (int np = 0; np < 4; np++) {
                const uint32_t off =
                    SWZ128((uint32_t)((wn * 64 + np * 16 + (lid & 15)) * 128) + cb);
                ldsm4(bh  + np * 4, base + OFF_BH + off);
                ldsm4(blo + np * 4, base + OFF_BL + off);
            }
#pragma unroll
            for (int mt = 0; mt < 4; mt++) {
                const uint32_t off =
                    SWZ128((uint32_t)((wm * 64 + mt * 16 + (lid & 15)) * 128) + cb);
                uint32_t ah[4], al[4];
                ldsm4(ah, base + OFF_AH + off);
                ldsm4(al, base + OFF_AL + off);
                // term-grouped: 8 independent accumulators between reuses
#pragma unroll
                for (int nt = 0; nt < 8; nt++) {
                    const int np = nt >> 1, q = nt & 1;
                    mma16816(acc[mt][nt], ah, bh[np * 4 + q], bh[np * 4 + 2 + q]);   // hi*hi
                }
#pragma unroll
                for (int nt = 0; nt < 8; nt++) {
                    const int np = nt >> 1, q = nt & 1;
                    mma16816(acc[mt][nt], al, bh[np * 4 + q], bh[np * 4 + 2 + q]);   // lo*hi
                }
#pragma unroll
                for (int nt = 0; nt < 8; nt++) {
                    const int np = nt >> 1, q = nt & 1;
                    mma16816(acc[mt][nt], ah, blo[np * 4 + q], blo[np * 4 + 2 + q]); // hi*lo
                }
            }
        }
        __syncthreads();
        if (s + 2 < nst) load_stage(s + 2);
        else CP_COMMIT();  // keep commit-group count uniform
    }

    // ---------------- epilogue ----------------
    const int gq = lid >> 2;   // row-in-group
    const int rq = lid & 3;    // col pair index
    float2 bv[8];
#pragma unroll
    for (int nt = 0; nt < 8; nt++) {
        const int col = n0 + wn * 64 + nt * 8 + rq * 2;
        bv[nt] = *reinterpret_cast<const float2*>(bias + (size_t)e * Ntot + col);
    }

#pragma unroll
    for (int mt = 0; mt < 4; mt++) {
#pragma unroll
        for (int nt = 0; nt < 8; nt++) {
            const int lr0 = wm * 64 + mt * 16 + gq;     // local rows lr0, lr0+8
            const int col = n0 + wn * 64 + nt * 8 + rq * 2;
            float c0 = acc[mt][nt][0] + bv[nt].x;
            float c1 = acc[mt][nt][1] + bv[nt].y;
            float c2 = acc[mt][nt][2] + bv[nt].x;
            float c3 = acc[mt][nt][3] + bv[nt].y;
            if (SOFTSIGN) {
                c0 = c0 / (1.0f + fabsf(c0));
                c1 = c1 / (1.0f + fabsf(c1));
                c2 = c2 / (1.0f + fabsf(c2));
                c3 = c3 / (1.0f + fabsf(c3));
                __nv_bfloat16 h0 = __float2bfloat16(c0), h1 = __float2bfloat16(c1);
                __nv_bfloat16 h2 = __float2bfloat16(c2), h3 = __float2bfloat16(c3);
                __nv_bfloat16 l0 = __float2bfloat16(c0 - __bfloat162float(h0));
                __nv_bfloat16 l1 = __float2bfloat16(c1 - __bfloat162float(h1));
                __nv_bfloat16 l2 = __float2bfloat16(c2 - __bfloat162float(h2));
                __nv_bfloat16 l3 = __float2bfloat16(c3 - __bfloat162float(h3));
                if (row0 + lr0 < rowend) {
                    size_t o0 = (size_t)(row0 + lr0) * Ntot + col;
                    *reinterpret_cast<__nv_bfloat162*>(outH + o0) = __nv_bfloat162(h0, h1);
                    *reinterpret_cast<__nv_bfloat162*>(outL + o0) = __nv_bfloat162(l0, l1);
                }
                if (row0 + lr0 + 8 < rowend) {
                    size_t o1 = (size_t)(row0 + lr0 + 8) * Ntot + col;
                    *reinterpret_cast<__nv_bfloat162*>(outH + o1) = __nv_bfloat162(h2, h3);
                    *reinterpret_cast<__nv_bfloat162*>(outL + o1) = __nv_bfloat162(l2, l3);
                }
            } else {
                const int d0 = rm[lr0];
                const int d1 = rm[lr0 + 8];
                if (d0 >= 0)
                    *reinterpret_cast<float2*>(outF + (size_t)d0 * Ntot + col) =
                        make_float2(c0, c1);
                if (d1 >= 0)
                    *reinterpret_cast<float2*>(outF + (size_t)d1 * Ntot + col) =
                        make_float2(c2, c3);
            }
        }
    }
}

// ---------------- host launcher ----------------
extern "C" void kernel_launch(void* const* d_in, const int* in_sizes, int n_in,
                              void* d_out, int out_size)
{
    const float* x   = (const float*)d_in[0];
    const int*   eid = (const int*)d_in[1];
    const float* W1  = (const float*)d_in[2];
    const float* b1  = (const float*)d_in[3];
    const float* W2  = (const float*)d_in[4];
    const float* b2  = (const float*)d_in[5];
    float* out = (float*)d_out;

    __nv_bfloat16 *xh, *xl, *w1h, *w1l, *w2h, *w2l, *ah, *al;
    cudaGetSymbolAddress((void**)&xh,  g_xh);
    cudaGetSymbolAddress((void**)&xl,  g_xl);
    cudaGetSymbolAddress((void**)&w1h, g_w1h);
    cudaGetSymbolAddress((void**)&w1l, g_w1l);
    cudaGetSymbolAddress((void**)&w2h, g_w2h);
    cudaGetSymbolAddress((void**)&w2l, g_w2l);
    cudaGetSymbolAddress((void**)&ah,  g_ah);
    cudaGetSymbolAddress((void**)&al,  g_al);

    cudaFuncSetAttribute(mma_gemm<true>,
                         cudaFuncAttributeMaxDynamicSharedMemorySize, SMEM_DYN);
    cudaFuncSetAttribute(mma_gemm<false>,
                         cudaFuncAttributeMaxDynamicSharedMemorySize, SMEM_DYN);

    // 1) expert sort / tile table / rowmap
    prep_kernel<<<1, 256>>>(eid);
    // 2) x -> bf16 hi/lo
    {
        int n4 = (TOTAL_ROWS * N_IN) / 4;
        convert_x_kernel<<<(n4 + 255) / 256, 256>>>(x, xh, xl, n4);
    }
    // 3) weights: transpose + split
    {
        dim3 blk(32, 32);
        convert_w_kernel<<<dim3(H_MID / 32, N_IN / 32, E_NUM), blk>>>(W1, w1h, w1l, N_IN, H_MID);
        convert_w_kernel<<<dim3(P_OUT / 32, H_MID / 32, E_NUM), blk>>>(W2, w2h, w2l, H_MID, P_OUT);
    }
    // 4) GEMM1: x rows (gathered) @ W1[e] -> softsign -> packed act hi/lo
    mma_gemm<true><<<dim3(H_MID / 256, MAXTILES), 256, SMEM_DYN>>>(
        xh, xl, w1h, w1l, b1, nullptr, ah, al, /*K=*/N_IN, /*Ntot=*/H_MID);
    // 5) GEMM2: packed act @ W2[e] -> scatter fp32 out
    mma_gemm<false><<<dim3(P_OUT / 256, MAXTILES), 256, SMEM_DYN>>>(
        ah, al, w2h, w2l, b2, out, nullptr, nullptr, /*K=*/H_MID, /*Ntot=*/P_OUT);
}

// round 6
// speedup vs baseline: 2.3428x; 1.0403x over previous
#include <cuda_runtime.h>
#include <cuda_bf16.h>
#include <cstdint>

// Problem constants: E=8, N=512(K1), H=1024, P=512, F=100, B=128
#define E_NUM    8
#define B_TRIALS 128
#define F_BINS   100
#define N_IN     512
#define H_MID    1024
#define P_OUT    512
#define TOTAL_ROWS (B_TRIALS * F_BINS)   // 12800 packed rows
#define ACT_ROWS   13056                  // padded
#define MAXTILES   112

// ---------------- device scratch ----------------
__device__ __nv_bfloat16 g_xh[(size_t)TOTAL_ROWS * N_IN];
__device__ __nv_bfloat16 g_xl[(size_t)TOTAL_ROWS * N_IN];
__device__ __nv_bfloat16 g_w1h[(size_t)E_NUM * H_MID * N_IN];   // [E, N(out), K] K-major
__device__ __nv_bfloat16 g_w1l[(size_t)E_NUM * H_MID * N_IN];
__device__ __nv_bfloat16 g_w2h[(size_t)E_NUM * P_OUT * H_MID];
__device__ __nv_bfloat16 g_w2l[(size_t)E_NUM * P_OUT * H_MID];
__device__ __nv_bfloat16 g_ah[(size_t)ACT_ROWS * H_MID];
__device__ __nv_bfloat16 g_al[(size_t)ACT_ROWS * H_MID];

__device__ int  g_order[B_TRIALS];
__device__ int  g_rowmap[TOTAL_ROWS];
__device__ int4 g_tiles[MAXTILES];
__device__ int  g_ntiles;

// ---------------- low-level helpers ----------------
__device__ __forceinline__ uint32_t smem_to_u32(const void* p) {
    uint32_t a;
    asm("{ .reg .u64 t; cvta.to.shared.u64 t, %1; cvt.u32.u64 %0, t; }"
        : "=r"(a) : "l"(p));
    return a;
}
#define SWZ128(o) ((o) ^ (((o) >> 3) & 0x70))

__device__ __forceinline__ void cp16(uint32_t dst, const void* src, uint32_t src_sz) {
    asm volatile("cp.async.cg.shared.global [%0], [%1], 16, %2;"
                 :: "r"(dst), "l"(src), "r"(src_sz) : "memory");
}
#define CP_COMMIT() asm volatile("cp.async.commit_group;" ::: "memory")
#define CP_WAIT1()  asm volatile("cp.async.wait_group 1;" ::: "memory")

__device__ __forceinline__ void ldsm4(uint32_t* r, uint32_t addr) {
    asm volatile("ldmatrix.sync.aligned.m8n8.x4.shared.b16 {%0,%1,%2,%3}, [%4];"
                 : "=r"(r[0]), "=r"(r[1]), "=r"(r[2]), "=r"(r[3]) : "r"(addr));
}
__device__ __forceinline__ void mma16816(float* c, const uint32_t* a,
                                         uint32_t b0, uint32_t b1) {
    asm volatile(
        "mma.sync.aligned.m16n8k16.row.col.f32.bf16.bf16.f32 "
        "{%0,%1,%2,%3}, {%4,%5,%6,%7}, {%8,%9}, {%0,%1,%2,%3};"
        : "+f"(c[0]), "+f"(c[1]), "+f"(c[2]), "+f"(c[3])
        : "r"(a[0]), "r"(a[1]), "r"(a[2]), "r"(a[3]), "r"(b0), "r"(b1));
}

// ---------------- prep kernel ----------------
__global__ void prep_kernel(const int* __restrict__ eid) {
    __shared__ int cnt[E_NUM], off[E_NUM];
    const int tid = threadIdx.x;
    if (tid < E_NUM) cnt[tid] = 0;
    __syncthreads();
    if (tid < B_TRIALS) atomicAdd(&cnt[eid[tid]], 1);
    __syncthreads();
    if (tid == 0) {
        int o = 0;
        for (int g = 0; g < E_NUM; g++) { off[g] = o; o += cnt[g]; }
        int c[E_NUM];
        for (int g = 0; g < E_NUM; g++) c[g] = 0;
        for (int i = 0; i < B_TRIALS; i++) {
            int g = eid[i];
            g_order[off[g] + c[g]++] = i;
        }
        int t = 0;
        for (int g = 0; g < E_NUM; g++) {
            int r0 = off[g] * F_BINS;
            int r1 = (off[g] + cnt[g]) * F_BINS;
            for (int r = r0; r < r1; r += 128)
                g_tiles[t++] = make_int4(g, r, r1, 0);
        }
        g_ntiles = t;
        for (; t < MAXTILES; t++) g_tiles[t] = make_int4(0, 0, 0, 0);
    }
    __syncthreads();
    for (int j = tid; j < TOTAL_ROWS; j += blockDim.x)
        g_rowmap[j] = g_order[j / F_BINS] * F_BINS + (j % F_BINS);
}

// ---------------- conversion kernels ----------------
__global__ void convert_x_kernel(const float* __restrict__ x,
                                 __nv_bfloat16* __restrict__ xh,
                                 __nv_bfloat16* __restrict__ xl, int n4) {
    int i = blockIdx.x * blockDim.x + threadIdx.x;
    if (i >= n4) return;
    float4 v = reinterpret_cast<const float4*>(x)[i];
    float f[4] = {v.x, v.y, v.z, v.w};
    __nv_bfloat16 hb[4], lb[4];
#pragma unroll
    for (int j = 0; j < 4; j++) {
        hb[j] = __float2bfloat16(f[j]);
        lb[j] = __float2bfloat16(f[j] - __bfloat162float(hb[j]));
    }
    reinterpret_cast<uint2*>(xh)[i] = *reinterpret_cast<uint2*>(hb);
    reinterpret_cast<uint2*>(xl)[i] = *reinterpret_cast<uint2*>(lb);
}

// W [E,K,Nt] fp32 -> Wh/Wl [E,Nt,K] bf16 (transpose + hi/lo split)
// R4-proven version: 32x32 block, one element per thread.
__global__ void convert_w_kernel(const float* __restrict__ W,
                                 __nv_bfloat16* __restrict__ Wh,
                                 __nv_bfloat16* __restrict__ Wl, int K, int Nt) {
    __shared__ float t[32][33];
    int e  = blockIdx.z;
    int n0 = blockIdx.x * 32;
    int k0 = blockIdx.y * 32;
    const float* src = W + ((size_t)e * K + k0) * Nt + n0;
    t[threadIdx.y][threadIdx.x] = src[(size_t)threadIdx.y * Nt + threadIdx.x];
    __syncthreads();
    float v = t[threadIdx.x][threadIdx.y];  // = W[e][k0+tx][n0+ty]
    __nv_bfloat16 h = __float2bfloat16(v);
    __nv_bfloat16 l = __float2bfloat16(v - __bfloat162float(h));
    size_t dst = ((size_t)e * Nt + (n0 + threadIdx.y)) * K + k0 + threadIdx.x;
    Wh[dst] = h;
    Wl[dst] = l;
}

// ---------------- grouped bf16 hi/lo mma.sync GEMM (expert-packed, 16 warps) ----------------
// CTA tile: M=128 x N=256, BK=64 (128B rows, SW128). 512 threads, warp tile 32x64.
#define OFF_AH   0
#define OFF_AL   16384
#define OFF_BH   32768
#define OFF_BL   65536
#define STAGE_SZ 98304
#define SMEM_DYN (2 * STAGE_SZ)

template <bool SOFTSIGN>
__global__ __launch_bounds__(512, 1)
void mma_gemm(const __nv_bfloat16* __restrict__ Ah, const __nv_bfloat16* __restrict__ Al,
              const __nv_bfloat16* __restrict__ Bh, const __nv_bfloat16* __restrict__ Bl,
              const float* __restrict__ bias,
              float* __restrict__ outF,
              __nv_bfloat16* __restrict__ outH, __nv_bfloat16* __restrict__ outL,
              int K, int Ntot)
{
    if ((int)blockIdx.y >= g_ntiles) return;
    const int4 tt     = g_tiles[blockIdx.y];
    const int  e      = tt.x;
    const int  row0   = tt.y;
    const int  rowend = tt.z;

    extern __shared__ __align__(1024) char smem[];
    __shared__ int rm[128];
    const uint32_t sb = smem_to_u32(smem);
    const int tid = threadIdx.x;
    const int wid = tid >> 5;
    const int lid = tid & 31;
    const int wm  = wid & 3;    // warp row (4) -> 32 rows each
    const int wn  = wid >> 2;   // warp col (4) -> 64 cols each
    const int n0  = blockIdx.x * 256;

    if (tid < 128) {
        const int r = row0 + tid;
        rm[tid] = (r < rowend) ? g_rowmap[r] : -1;
    }
    __syncthreads();

    const __nv_bfloat16* aSrc[2] = {Ah, Al};
    const __nv_bfloat16* bSrc[2] = {Bh, Bl};
    const int nst = K >> 6;

    auto load_stage = [&](int s) {
        const int k0 = s << 6;
        const uint32_t tb = sb + (uint32_t)(s & 1) * STAGE_SZ;
        // A hi+lo: 2048 slots / 512 thr = 4 iters
#pragma unroll
        for (int it = 0; it < 4; it++) {
            int slot = it * 512 + tid;
            int arr  = slot >> 10;
            int idx  = slot & 1023;
            int r    = idx >> 3;
            int c    = idx & 7;
            const __nv_bfloat16* src;
            uint32_t sz;
            if (SOFTSIGN) {
                int sr = rm[r];
                src = aSrc[arr] + (size_t)(sr < 0 ? 0 : sr) * K + k0 + c * 8;
                sz  = (sr < 0) ? 0u : 16u;
            } else {
                src = aSrc[arr] + (size_t)(row0 + r) * K + k0 + c * 8;
                sz  = 16u;
            }
            uint32_t dst = tb + (arr ? OFF_AL : OFF_AH) + SWZ128((uint32_t)(r * 128 + c * 16));
            cp16(dst, src, sz);
        }
        // B hi+lo: 4096 slots / 512 thr = 8 iters
#pragma unroll
        for (int it = 0; it < 8; it++) {
            int slot = it * 512 + tid;
            int arr  = slot >> 11;
            int idx  = slot & 2047;
            int r    = idx >> 3;
            int c    = idx & 7;
            const __nv_bfloat16* src =
                bSrc[arr] + ((size_t)e * Ntot + n0 + r) * K + k0 + c * 8;
            uint32_t dst = tb + (arr ? OFF_BL : OFF_BH) + SWZ128((uint32_t)(r * 128 + c * 16));
            cp16(dst, src, 16u);
        }
        CP_COMMIT();
    };

    float acc[2][8][4];
#pragma unroll
    for (int mt = 0; mt < 2; mt++)
#pragma unroll
        for (int nt = 0; nt < 8; nt++)
#pragma unroll
            for (int q = 0; q < 4; q++) acc[mt][nt][q] = 0.0f;

    load_stage(0);
    load_stage(1);

    for (int s = 0; s < nst; s++) {
        CP_WAIT1();
        __syncthreads();
        const uint32_t base = sb + (uint32_t)(s & 1) * STAGE_SZ;

#pragma unroll
        for (int kk = 0; kk < 4; kk++) {
            const uint32_t cb = (uint32_t)(kk * 32 + ((lid >> 4) << 4));
            // A frags for this warp's 32 rows (mt=0,1), hi+lo
            uint32_t ah[2][4], al[2][4];
#pragma unroll
            for (int mt = 0; mt < 2; mt++) {
                const uint32_t off =
                    SWZ128((uint32_t)((wm * 32 + mt * 16 + (lid & 15)) * 128) + cb);
                ldsm4(ah[mt], base + OFF_AH + off);
                ldsm4(al[mt], base + OFF_AL + off);
            }
#pragma unroll
            for (int np = 0; np < 4; np++) {
                const uint32_t off =
                    SWZ128((uint32_t)((wn * 64 + np * 16 + (lid & 15)) * 128) + cb);
                uint32_t bh[4], blo[4];
                ldsm4(bh,  base + OFF_BH + off);
                ldsm4(blo, base + OFF_BL + off);
                const int nt0 = np * 2;
#pragma unroll
                for (int q = 0; q < 2; q++) {
                    mma16816(acc[0][nt0 + q], ah[0], bh[q], bh[2 + q]);
                    mma16816(acc[1][nt0 + q], ah[1], bh[q], bh[2 + q]);
                }
#pragma unroll
                for (int q = 0; q < 2; q++) {
                    mma16816(acc[0][nt0 + q], al[0], bh[q], bh[2 + q]);
                    mma16816(acc[1][nt0 + q], al[1], bh[q], bh[2 + q]);
                }
#pragma unroll
                for (int q = 0; q < 2; q++) {
                    mma16816(acc[0][nt0 + q], ah[0], blo[q], blo[2 + q]);
                    mma16816(acc[1][nt0 + q], ah[1], blo[q], blo[2 + q]);
                }
            }
        }
        __syncthreads();
        if (s + 2 < nst) load_stage(s + 2);
        else CP_COMMIT();
    }

    // ---------------- epilogue ----------------
    const int gq = lid >> 2;
    const int rq = lid & 3;
    float2 bv[8];
#pragma unroll
    for (int nt = 0; nt < 8; nt++) {
        const int col = n0 + wn * 64 + nt * 8 + rq * 2;
        bv[nt] = *reinterpret_cast<const float2*>(bias + (size_t)e * Ntot + col);
    }

#pragma unroll
    for (int mt = 0; mt < 2; mt++) {
#pragma unroll
        for (int nt = 0; nt < 8; nt++) {
            const int lr0 = wm * 32 + mt * 16 + gq;
            const int col = n0 + wn * 64 + nt * 8 + rq * 2;
            float c0 = acc[mt][nt][0] + bv[nt].x;
            float c1 = acc[mt][nt][1] + bv[nt].y;
            float c2 = acc[mt][nt][2] + bv[nt].x;
            float c3 = acc[mt][nt][3] + bv[nt].y;
            if (SOFTSIGN) {
                c0 = c0 / (1.0f + fabsf(c0));
                c1 = c1 / (1.0f + fabsf(c1));
                c2 = c2 / (1.0f + fabsf(c2));
                c3 = c3 / (1.0f + fabsf(c3));
                __nv_bfloat16 h0 = __float2bfloat16(c0), h1 = __float2bfloat16(c1);
                __nv_bfloat16 h2 = __float2bfloat16(c2), h3 = __float2bfloat16(c3);
                __nv_bfloat16 l0 = __float2bfloat16(c0 - __bfloat162float(h0));
                __nv_bfloat16 l1 = __float2bfloat16(c1 - __bfloat162float(h1));
                __nv_bfloat16 l2 = __float2bfloat16(c2 - __bfloat162float(h2));
                __nv_bfloat16 l3 = __float2bfloat16(c3 - __bfloat162float(h3));
                if (row0 + lr0 < rowend) {
                    size_t o0 = (size_t)(row0 + lr0) * Ntot + col;
                    *reinterpret_cast<__nv_bfloat162*>(outH + o0) = __nv_bfloat162(h0, h1);
                    *reinterpret_cast<__nv_bfloat162*>(outL + o0) = __nv_bfloat162(l0, l1);
                }
                if (row0 + lr0 + 8 < rowend) {
                    size_t o1 = (size_t)(row0 + lr0 + 8) * Ntot + col;
                    *reinterpret_cast<__nv_bfloat162*>(outH + o1) = __nv_bfloat162(h2, h3);
                    *reinterpret_cast<__nv_bfloat162*>(outL + o1) = __nv_bfloat162(l2, l3);
                }
            } else {
                const int d0 = rm[lr0];
                const int d1 = rm[lr0 + 8];
                if (d0 >= 0)
                    *reinterpret_cast<float2*>(outF + (size_t)d0 * Ntot + col) =
                        make_float2(c0, c1);
                if (d1 >= 0)
                    *reinterpret_cast<float2*>(outF + (size_t)d1 * Ntot + col) =
                        make_float2(c2, c3);
            }
        }
    }
}

// ---------------- host launcher ----------------
extern "C" void kernel_launch(void* const* d_in, const int* in_sizes, int n_in,
                              void* d_out, int out_size)
{
    const float* x   = (const float*)d_in[0];
    const int*   eid = (const int*)d_in[1];
    const float* W1  = (const float*)d_in[2];
    const float* b1  = (const float*)d_in[3];
    const float* W2  = (const float*)d_in[4];
    const float* b2  = (const float*)d_in[5];
    float* out = (float*)d_out;

    __nv_bfloat16 *xh, *xl, *w1h, *w1l, *w2h, *w2l, *ah, *al;
    cudaGetSymbolAddress((void**)&xh,  g_xh);
    cudaGetSymbolAddress((void**)&xl,  g_xl);
    cudaGetSymbolAddress((void**)&w1h, g_w1h);
    cudaGetSymbolAddress((void**)&w1l, g_w1l);
    cudaGetSymbolAddress((void**)&w2h, g_w2h);
    cudaGetSymbolAddress((void**)&w2l, g_w2l);
    cudaGetSymbolAddress((void**)&ah,  g_ah);
    cudaGetSymbolAddress((void**)&al,  g_al);

    cudaFuncSetAttribute(mma_gemm<true>,
                         cudaFuncAttributeMaxDynamicSharedMemorySize, SMEM_DYN);
    cudaFuncSetAttribute(mma_gemm<false>,
                         cudaFuncAttributeMaxDynamicSharedMemorySize, SMEM_DYN);

    // 1) expert sort / tile table / rowmap
    prep_kernel<<<1, 256>>>(eid);
    // 2) x -> bf16 hi/lo
    {
        int n4 = (TOTAL_ROWS * N_IN) / 4;
        convert_x_kernel<<<(n4 + 255) / 256, 256>>>(x, xh, xl, n4);
    }
    // 3) weights: transpose + split (proven 32x32 version)
    {
        dim3 blk(32, 32);
        convert_w_kernel<<<dim3(H_MID / 32, N_IN / 32, E_NUM), blk>>>(W1, w1h, w1l, N_IN, H_MID);
        convert_w_kernel<<<dim3(P_OUT / 32, H_MID / 32, E_NUM), blk>>>(W2, w2h, w2l, H_MID, P_OUT);
    }
    // 4) GEMM1
    mma_gemm<true><<<dim3(H_MID / 256, MAXTILES), 512, SMEM_DYN>>>(
        xh, xl, w1h, w1l, b1, nullptr, ah, al, /*K=*/N_IN, /*Ntot=*/H_MID);
    // 5) GEMM2
    mma_gemm<false><<<dim3(P_OUT / 256, MAXTILES), 512, SMEM_DYN>>>(
        ah, al, w2h, w2l, b2, out, nullptr, nullptr, /*K=*/H_MID, /*Ntot=*/P_OUT);
}

// round 7
// speedup vs baseline: 3.0805x; 1.3148x over previous
#include <cuda_runtime.h>
#include <cuda_fp16.h>
#include <cstdint>

// Problem constants: E=8, N=512(K1), H=1024, P=512, F=100, B=128
#define E_NUM    8
#define B_TRIALS 128
#define F_BINS   100
#define N_IN     512
#define H_MID    1024
#define P_OUT    512
#define TOTAL_ROWS (B_TRIALS * F_BINS)   // 12800 packed rows
#define ACT_ROWS   13056                  // padded
#define MAXTILES   112

// ---------------- device scratch ----------------
__device__ __half g_xh[(size_t)TOTAL_ROWS * N_IN];
__device__ __half g_xl[(size_t)TOTAL_ROWS * N_IN];
__device__ __half g_w1[(size_t)E_NUM * H_MID * N_IN];   // [E, N(out), K] K-major, fp16
__device__ __half g_w2[(size_t)E_NUM * P_OUT * H_MID];
__device__ __half g_ah[(size_t)ACT_ROWS * H_MID];       // act hi fp16
__device__ __half g_al[(size_t)ACT_ROWS * H_MID];       // act lo fp16

__device__ int  g_order[B_TRIALS];
__device__ int  g_rowmap[TOTAL_ROWS];
__device__ int4 g_tiles[MAXTILES];
__device__ int  g_ntiles;

// ---------------- low-level helpers ----------------
__device__ __forceinline__ uint32_t smem_to_u32(const void* p) {
    uint32_t a;
    asm("{ .reg .u64 t; cvta.to.shared.u64 t, %1; cvt.u32.u64 %0, t; }"
        : "=r"(a) : "l"(p));
    return a;
}
#define SWZ128(o) ((o) ^ (((o) >> 3) & 0x70))

__device__ __forceinline__ void cp16(uint32_t dst, const void* src, uint32_t src_sz) {
    asm volatile("cp.async.cg.shared.global [%0], [%1], 16, %2;"
                 :: "r"(dst), "l"(src), "r"(src_sz) : "memory");
}
#define CP_COMMIT() asm volatile("cp.async.commit_group;" ::: "memory")
#define CP_WAIT2()  asm volatile("cp.async.wait_group 2;" ::: "memory")

__device__ __forceinline__ void ldsm4(uint32_t* r, uint32_t addr) {
    asm volatile("ldmatrix.sync.aligned.m8n8.x4.shared.b16 {%0,%1,%2,%3}, [%4];"
                 : "=r"(r[0]), "=r"(r[1]), "=r"(r[2]), "=r"(r[3]) : "r"(addr));
}
__device__ __forceinline__ void mma16816(float* c, const uint32_t* a,
                                         uint32_t b0, uint32_t b1) {
    asm volatile(
        "mma.sync.aligned.m16n8k16.row.col.f32.f16.f16.f32 "
        "{%0,%1,%2,%3}, {%4,%5,%6,%7}, {%8,%9}, {%0,%1,%2,%3};"
        : "+f"(c[0]), "+f"(c[1]), "+f"(c[2]), "+f"(c[3])
        : "r"(a[0]), "r"(a[1]), "r"(a[2]), "r"(a[3]), "r"(b0), "r"(b1));
}

// ---------------- prep kernel ----------------
__global__ void prep_kernel(const int* __restrict__ eid) {
    __shared__ int cnt[E_NUM], off[E_NUM];
    const int tid = threadIdx.x;
    if (tid < E_NUM) cnt[tid] = 0;
    __syncthreads();
    if (tid < B_TRIALS) atomicAdd(&cnt[eid[tid]], 1);
    __syncthreads();
    if (tid == 0) {
        int o = 0;
        for (int g = 0; g < E_NUM; g++) { off[g] = o; o += cnt[g]; }
        int c[E_NUM];
        for (int g = 0; g < E_NUM; g++) c[g] = 0;
        for (int i = 0; i < B_TRIALS; i++) {
            int g = eid[i];
            g_order[off[g] + c[g]++] = i;
        }
        int t = 0;
        for (int g = 0; g < E_NUM; g++) {
            int r0 = off[g] * F_BINS;
            int r1 = (off[g] + cnt[g]) * F_BINS;
            for (int r = r0; r < r1; r += 128)
                g_tiles[t++] = make_int4(g, r, r1, 0);
        }
        g_ntiles = t;
        for (; t < MAXTILES; t++) g_tiles[t] = make_int4(0, 0, 0, 0);
    }
    __syncthreads();
    for (int j = tid; j < TOTAL_ROWS; j += blockDim.x)
        g_rowmap[j] = g_order[j / F_BINS] * F_BINS + (j % F_BINS);
}

// ---------------- conversion kernels ----------------
__global__ void convert_x_kernel(const float* __restrict__ x,
                                 __half* __restrict__ xh,
                                 __half* __restrict__ xl, int n4) {
    int i = blockIdx.x * blockDim.x + threadIdx.x;
    if (i >= n4) return;
    float4 v = reinterpret_cast<const float4*>(x)[i];
    float f[4] = {v.x, v.y, v.z, v.w};
    __half hb[4], lb[4];
#pragma unroll
    for (int j = 0; j < 4; j++) {
        hb[j] = __float2half_rn(f[j]);
        lb[j] = __float2half_rn(f[j] - __half2float(hb[j]));
    }
    reinterpret_cast<uint2*>(xh)[i] = *reinterpret_cast<uint2*>(hb);
    reinterpret_cast<uint2*>(xl)[i] = *reinterpret_cast<uint2*>(lb);
}

// W [E,K,Nt] fp32 -> Wt [E,Nt,K] fp16 (transpose, single precision term)
__global__ void convert_w_kernel(const float* __restrict__ W,
                                 __half* __restrict__ Wt, int K, int Nt) {
    __shared__ float t[32][33];
    int e  = blockIdx.z;
    int n0 = blockIdx.x * 32;
    int k0 = blockIdx.y * 32;
    const float* src = W + ((size_t)e * K + k0) * Nt + n0;
    t[threadIdx.y][threadIdx.x] = src[(size_t)threadIdx.y * Nt + threadIdx.x];
    __syncthreads();
    float v = t[threadIdx.x][threadIdx.y];  // = W[e][k0+tx][n0+ty]
    Wt[((size_t)e * Nt + (n0 + threadIdx.y)) * K + k0 + threadIdx.x] = __float2half_rn(v);
}

// ---------------- grouped fp16 2-term mma.sync GEMM (expert-packed, 16 warps) ----------------
// CTA tile: M=128 x N=256, BK=64 (128B rows, SW128). 512 threads, warp tile 32x64.
// smem per stage: A_hi 16K | A_lo 16K | B 32K = 64KB, 3-stage pipeline (192KB).
#define OFF_AH   0
#define OFF_AL   16384
#define OFF_B    32768
#define STAGE_SZ 65536
#define SMEM_DYN (3 * STAGE_SZ)

template <bool SOFTSIGN>
__global__ __launch_bounds__(512, 1)
void mma_gemm(const __half* __restrict__ Ah, const __half* __restrict__ Al,
              const __half* __restrict__ Bw,
              const float* __restrict__ bias,
              float* __restrict__ outF,
              __half* __restrict__ outH, __half* __restrict__ outL,
              int K, int Ntot)
{
    if ((int)blockIdx.y >= g_ntiles) return;
    const int4 tt     = g_tiles[blockIdx.y];
    const int  e      = tt.x;
    const int  row0   = tt.y;
    const int  rowend = tt.z;

    extern __shared__ __align__(1024) char smem[];
    __shared__ int rm[128];
    const uint32_t sb = smem_to_u32(smem);
    const int tid = threadIdx.x;
    const int wid = tid >> 5;
    const int lid = tid & 31;
    const int wm  = wid & 3;    // warp row (4) -> 32 rows each
    const int wn  = wid >> 2;   // warp col (4) -> 64 cols each
    const int n0  = blockIdx.x * 256;

    if (tid < 128) {
        const int r = row0 + tid;
        rm[tid] = (r < rowend) ? g_rowmap[r] : -1;
    }
    __syncthreads();

    const __half* aSrc[2] = {Ah, Al};
    const int nst = K >> 6;

    auto load_stage = [&](int s) {
        const int k0 = s << 6;
        const uint32_t tb = sb + (uint32_t)(s % 3) * STAGE_SZ;
        // A hi+lo: 2048 slots; B: 2048 slots; total 4096 / 512 thr = 8 iters
#pragma unroll
        for (int it = 0; it < 8; it++) {
            int slot = it * 512 + tid;
            if (slot < 2048) {            // A
                int arr = slot >> 10;
                int idx = slot & 1023;
                int r   = idx >> 3;
                int c   = idx & 7;
                const __half* src;
                uint32_t sz;
                if (SOFTSIGN) {
                    int sr = rm[r];
                    src = aSrc[arr] + (size_t)(sr < 0 ? 0 : sr) * K + k0 + c * 8;
                    sz  = (sr < 0) ? 0u : 16u;
                } else {
                    src = aSrc[arr] + (size_t)(row0 + r) * K + k0 + c * 8;
                    sz  = 16u;
                }
                uint32_t dst = tb + (arr ? OFF_AL : OFF_AH) +
                               SWZ128((uint32_t)(r * 128 + c * 16));
                cp16(dst, src, sz);
            } else {                      // B
                int idx = slot - 2048;
                int r   = idx >> 3;
                int c   = idx & 7;
                const __half* src =
                    Bw + ((size_t)e * Ntot + n0 + r) * K + k0 + c * 8;
                uint32_t dst = tb + OFF_B + SWZ128((uint32_t)(r * 128 + c * 16));
                cp16(dst, src, 16u);
            }
        }
        CP_COMMIT();
    };

    float acc[2][8][4];
#pragma unroll
    for (int mt = 0; mt < 2; mt++)
#pragma unroll
        for (int nt = 0; nt < 8; nt++)
#pragma unroll
            for (int q = 0; q < 4; q++) acc[mt][nt][q] = 0.0f;

    load_stage(0);
    load_stage(1);
    load_stage(2);

    for (int s = 0; s < nst; s++) {
        CP_WAIT2();
        __syncthreads();
        const uint32_t base = sb + (uint32_t)(s % 3) * STAGE_SZ;

#pragma unroll
        for (int kk = 0; kk < 4; kk++) {
            const uint32_t cb = (uint32_t)(kk * 32 + ((lid >> 4) << 4));
            uint32_t ah[2][4], al[2][4];
#pragma unroll
            for (int mt = 0; mt < 2; mt++) {
                const uint32_t off =
                    SWZ128((uint32_t)((wm * 32 + mt * 16 + (lid & 15)) * 128) + cb);
                ldsm4(ah[mt], base + OFF_AH + off);
                ldsm4(al[mt], base + OFF_AL + off);
            }
#pragma unroll
            for (int np = 0; np < 4; np++) {
                const uint32_t off =
                    SWZ128((uint32_t)((wn * 64 + np * 16 + (lid & 15)) * 128) + cb);
                uint32_t bh[4];
                ldsm4(bh, base + OFF_B + off);
                const int nt0 = np * 2;
#pragma unroll
                for (int q = 0; q < 2; q++) {
                    mma16816(acc[0][nt0 + q], ah[0], bh[q], bh[2 + q]);
                    mma16816(acc[1][nt0 + q], ah[1], bh[q], bh[2 + q]);
                }
#pragma unroll
                for (int q = 0; q < 2; q++) {
                    mma16816(acc[0][nt0 + q], al[0], bh[q], bh[2 + q]);
                    mma16816(acc[1][nt0 + q], al[1], bh[q], bh[2 + q]);
                }
            }
        }
        __syncthreads();
        if (s + 3 < nst) load_stage(s + 3);
        else CP_COMMIT();
    }

    // ---------------- epilogue ----------------
    const int gq = lid >> 2;
    const int rq = lid & 3;
    float2 bv[8];
#pragma unroll
    for (int nt = 0; nt < 8; nt++) {
        const int col = n0 + wn * 64 + nt * 8 + rq * 2;
        bv[nt] = *reinterpret_cast<const float2*>(bias + (size_t)e * Ntot + col);
    }

#pragma unroll
    for (int mt = 0; mt < 2; mt++) {
#pragma unroll
        for (int nt = 0; nt < 8; nt++) {
            const int lr0 = wm * 32 + mt * 16 + gq;
            const int col = n0 + wn * 64 + nt * 8 + rq * 2;
            float c0 = acc[mt][nt][0] + bv[nt].x;
            float c1 = acc[mt][nt][1] + bv[nt].y;
            float c2 = acc[mt][nt][2] + bv[nt].x;
            float c3 = acc[mt][nt][3] + bv[nt].y;
            if (SOFTSIGN) {
                c0 = c0 / (1.0f + fabsf(c0));
                c1 = c1 / (1.0f + fabsf(c1));
                c2 = c2 / (1.0f + fabsf(c2));
                c3 = c3 / (1.0f + fabsf(c3));
                __half h0 = __float2half_rn(c0), h1 = __float2half_rn(c1);
                __half h2 = __float2half_rn(c2), h3 = __float2half_rn(c3);
                __half l0 = __float2half_rn(c0 - __half2float(h0));
                __half l1 = __float2half_rn(c1 - __half2float(h1));
                __half l2 = __float2half_rn(c2 - __half2float(h2));
                __half l3 = __float2half_rn(c3 - __half2float(h3));
                if (row0 + lr0 < rowend) {
                    size_t o0 = (size_t)(row0 + lr0) * Ntot + col;
                    *reinterpret_cast<__half2*>(outH + o0) = __half2(h0, h1);
                    *reinterpret_cast<__half2*>(outL + o0) = __half2(l0, l1);
                }
                if (row0 + lr0 + 8 < rowend) {
                    size_t o1 = (size_t)(row0 + lr0 + 8) * Ntot + col;
                    *reinterpret_cast<__half2*>(outH + o1) = __half2(h2, h3);
                    *reinterpret_cast<__half2*>(outL + o1) = __half2(l2, l3);
                }
            } else {
                const int d0 = rm[lr0];
                const int d1 = rm[lr0 + 8];
                if (d0 >= 0)
                    *reinterpret_cast<float2*>(outF + (size_t)d0 * Ntot + col) =
                        make_float2(c0, c1);
                if (d1 >= 0)
                    *reinterpret_cast<float2*>(outF + (size_t)d1 * Ntot + col) =
                        make_float2(c2, c3);
            }
        }
    }
}

// ---------------- host launcher ----------------
extern "C" void kernel_launch(void* const* d_in, const int* in_sizes, int n_in,
                              void* d_out, int out_size)
{
    const float* x   = (const float*)d_in[0];
    const int*   eid = (const int*)d_in[1];
    const float* W1  = (const float*)d_in[2];
    const float* b1  = (const float*)d_in[3];
    const float* W2  = (const float*)d_in[4];
    const float* b2  = (const float*)d_in[5];
    float* out = (float*)d_out;

    __half *xh, *xl, *w1, *w2, *ah, *al;
    cudaGetSymbolAddress((void**)&xh, g_xh);
    cudaGetSymbolAddress((void**)&xl, g_xl);
    cudaGetSymbolAddress((void**)&w1, g_w1);
    cudaGetSymbolAddress((void**)&w2, g_w2);
    cudaGetSymbolAddress((void**)&ah, g_ah);
    cudaGetSymbolAddress((void**)&al, g_al);

    cudaFuncSetAttribute(mma_gemm<true>,
                         cudaFuncAttributeMaxDynamicSharedMemorySize, SMEM_DYN);
    cudaFuncSetAttribute(mma_gemm<false>,
                         cudaFuncAttributeMaxDynamicSharedMemorySize, SMEM_DYN);

    // 1) expert sort / tile table / rowmap
    prep_kernel<<<1, 256>>>(eid);
    // 2) x -> fp16 hi/lo
    {
        int n4 = (TOTAL_ROWS * N_IN) / 4;
        convert_x_kernel<<<(n4 + 255) / 256, 256>>>(x, xh, xl, n4);
    }
    // 3) weights: transpose to fp16 (single term)
    {
        dim3 blk(32, 32);
        convert_w_kernel<<<dim3(H_MID / 32, N_IN / 32, E_NUM), blk>>>(W1, w1, N_IN, H_MID);
        convert_w_kernel<<<dim3(P_OUT / 32, H_MID / 32, E_NUM), blk>>>(W2, w2, H_MID, P_OUT);
    }
    // 4) GEMM1: x (hi+lo gathered) @ W1[e] -> softsign -> packed act hi/lo
    mma_gemm<true><<<dim3(H_MID / 256, MAXTILES), 512, SMEM_DYN>>>(
        xh, xl, w1, b1, nullptr, ah, al, /*K=*/N_IN, /*Ntot=*/H_MID);
    // 5) GEMM2: packed act (hi+lo) @ W2[e] -> scatter fp32 out
    mma_gemm<false><<<dim3(P_OUT / 256, MAXTILES), 512, SMEM_DYN>>>(
        ah, al, w2, b2, out, nullptr, nullptr, /*K=*/H_MID, /*Ntot=*/P_OUT);
}

// round 8
// speedup vs baseline: 3.7799x; 1.2271x over previous
#include <cuda_runtime.h>
#include <cuda_fp16.h>
#include <cstdint>

// Problem constants: E=8, N=512(K1), H=1024, P=512, F=100, B=128
#define E_NUM    8
#define B_TRIALS 128
#define F_BINS   100
#define N_IN     512
#define H_MID    1024
#define P_OUT    512
#define TOTAL_ROWS (B_TRIALS * F_BINS)   // 12800 packed rows
#define ACT_ROWS   13056                  // padded
#define MAXT128  120
#define MAXT64   224

// ---------------- device scratch ----------------
__device__ __half g_xh[(size_t)TOTAL_ROWS * N_IN];
__device__ __half g_xl[(size_t)TOTAL_ROWS * N_IN];
__device__ __half g_w1[(size_t)E_NUM * H_MID * N_IN];   // [E, N(out), K] K-major fp16
__device__ __half g_w2[(size_t)E_NUM * P_OUT * H_MID];
__device__ __half g_ah[(size_t)ACT_ROWS * H_MID];       // act hi fp16 (zero-init)
__device__ __half g_al[(size_t)ACT_ROWS * H_MID];       // act lo fp16

__device__ int  g_order[B_TRIALS];
__device__ int  g_rowmap[TOTAL_ROWS];
__device__ int4 g_t128[MAXT128];
__device__ int  g_n128;
__device__ int4 g_t64[MAXT64];
__device__ int  g_n64;

// ---------------- low-level helpers ----------------
__device__ __forceinline__ uint32_t smem_to_u32(const void* p) {
    uint32_t a;
    asm("{ .reg .u64 t; cvta.to.shared.u64 t, %1; cvt.u32.u64 %0, t; }"
        : "=r"(a) : "l"(p));
    return a;
}
#define SWZ128(o) ((o) ^ (((o) >> 3) & 0x70))

__device__ __forceinline__ void cp16(uint32_t dst, const void* src, uint32_t src_sz) {
    asm volatile("cp.async.cg.shared.global [%0], [%1], 16, %2;"
                 :: "r"(dst), "l"(src), "r"(src_sz) : "memory");
}
#define CP_COMMIT() asm volatile("cp.async.commit_group;" ::: "memory")
#define CP_WAIT1()  asm volatile("cp.async.wait_group 1;" ::: "memory")

__device__ __forceinline__ void ldsm4(uint32_t* r, uint32_t addr) {
    asm volatile("ldmatrix.sync.aligned.m8n8.x4.shared.b16 {%0,%1,%2,%3}, [%4];"
                 : "=r"(r[0]), "=r"(r[1]), "=r"(r[2]), "=r"(r[3]) : "r"(addr));
}
__device__ __forceinline__ void mma16816(float* c, const uint32_t* a,
                                         uint32_t b0, uint32_t b1) {
    asm volatile(
        "mma.sync.aligned.m16n8k16.row.col.f32.f16.f16.f32 "
        "{%0,%1,%2,%3}, {%4,%5,%6,%7}, {%8,%9}, {%0,%1,%2,%3};"
        : "+f"(c[0]), "+f"(c[1]), "+f"(c[2]), "+f"(c[3])
        : "r"(a[0]), "r"(a[1]), "r"(a[2]), "r"(a[3]), "r"(b0), "r"(b1));
}

// ---------------- prep kernel ----------------
__global__ void prep_kernel(const int* __restrict__ eid) {
    __shared__ int cnt[E_NUM], off[E_NUM];
    const int tid = threadIdx.x;
    if (tid < E_NUM) cnt[tid] = 0;
    __syncthreads();
    if (tid < B_TRIALS) atomicAdd(&cnt[eid[tid]], 1);
    __syncthreads();
    if (tid == 0) {
        int o = 0;
        for (int g = 0; g < E_NUM; g++) { off[g] = o; o += cnt[g]; }
        int c[E_NUM];
        for (int g = 0; g < E_NUM; g++) c[g] = 0;
        for (int i = 0; i < B_TRIALS; i++) {
            int g = eid[i];
            g_order[off[g] + c[g]++] = i;
        }
        int t = 0;
        for (int g = 0; g < E_NUM; g++) {
            int r0 = off[g] * F_BINS;
            int r1 = (off[g] + cnt[g]) * F_BINS;
            for (int r = r0; r < r1; r += 128)
                g_t128[t++] = make_int4(g, r, r1, 0);
        }
        g_n128 = t;
        for (; t < MAXT128; t++) g_t128[t] = make_int4(0, 0, 0, 0);
        t = 0;
        for (int g = 0; g < E_NUM; g++) {
            int r0 = off[g] * F_BINS;
            int r1 = (off[g] + cnt[g]) * F_BINS;
            for (int r = r0; r < r1; r += 64)
                g_t64[t++] = make_int4(g, r, r1, 0);
        }
        g_n64 = t;
        for (; t < MAXT64; t++) g_t64[t] = make_int4(0, 0, 0, 0);
    }
    __syncthreads();
    for (int j = tid; j < TOTAL_ROWS; j += blockDim.x)
        g_rowmap[j] = g_order[j / F_BINS] * F_BINS + (j % F_BINS);
}

// ---------------- conversion kernels ----------------
__global__ void convert_x_kernel(const float* __restrict__ x,
                                 __half* __restrict__ xh,
                                 __half* __restrict__ xl, int n4) {
    int i = blockIdx.x * blockDim.x + threadIdx.x;
    if (i >= n4) return;
    float4 v = reinterpret_cast<const float4*>(x)[i];
    float f[4] = {v.x, v.y, v.z, v.w};
    __half hb[4], lb[4];
#pragma unroll
    for (int j = 0; j < 4; j++) {
        hb[j] = __float2half_rn(f[j]);
        lb[j] = __float2half_rn(f[j] - __half2float(hb[j]));
    }
    reinterpret_cast<uint2*>(xh)[i] = *reinterpret_cast<uint2*>(hb);
    reinterpret_cast<uint2*>(xl)[i] = *reinterpret_cast<uint2*>(lb);
}

// W [E,K,Nt] fp32 -> Wt [E,Nt,K] fp16, 16B vectorized stores.
// tile: 64 k-rows x 32 n-cols, 256 threads.
__global__ void convert_w_kernel(const float* __restrict__ W,
                                 __half* __restrict__ Wt, int K, int Nt) {
    __shared__ float t[64][33];
    int e  = blockIdx.z;
    int n0 = blockIdx.x * 32;
    int k0 = blockIdx.y * 64;
    const float* src = W + ((size_t)e * K + k0) * Nt + n0;
#pragma unroll
    for (int i = 0; i < 8; i++) {
        int r = (threadIdx.x >> 5) + i * 8;   // 0..63 (k)
        int c = threadIdx.x & 31;             // 0..31 (n)
        t[r][c] = src[(size_t)r * Nt + c];
    }
    __syncthreads();
    int n  = threadIdx.x >> 3;   // 0..31
    int kc = threadIdx.x & 7;    // 0..7 (8 k each)
    __half h[8];
#pragma unroll
    for (int j = 0; j < 8; j++) h[j] = __float2half_rn(t[kc * 8 + j][n]);
    *reinterpret_cast<uint4*>(Wt + ((size_t)e * Nt + n0 + n) * K + k0 + kc * 8) =
        *reinterpret_cast<uint4*>(h);
}

// ---------------- grouped fp16 2-term mma.sync GEMM ----------------
// Template: MT in {128, 64}; N tile fixed 128; 256 threads (8 warps); 2 CTAs/SM.
// smem/stage: A(hi+lo) MT*256 B + B 16KB; 2 stages.
template <int MT, bool SOFTSIGN>
__global__ __launch_bounds__(256, 2)
void mma_gemm(const __half* __restrict__ Ah, const __half* __restrict__ Al,
              const __half* __restrict__ Bw,
              const float* __restrict__ bias,
              float* __restrict__ outF,
              __half* __restrict__ outH, __half* __restrict__ outL,
              int K, int Ntot)
{
    constexpr int MWARPS = MT / 32;            // 4 or 2
    constexpr int NWARPS = 8 / MWARPS;         // 2 or 4
    constexpr int WARP_N = 128 / NWARPS;       // 64 or 32
    constexpr int NP     = WARP_N / 16;        // 4 or 2
    constexpr int NT8    = WARP_N / 8;         // 8 or 4
    constexpr uint32_t OFF_AL = MT * 128;
    constexpr uint32_t OFF_B  = MT * 256;
    constexpr uint32_t STAGE  = MT * 256 + 16384;
    constexpr int A_SLOTS = MT * 16;           // hi+lo
    constexpr int SLOTS   = A_SLOTS + 1024;    // + B (128 rows x 8 chunks)
    constexpr int ITERS   = SLOTS / 256;

    const int ntiles = (MT == 128) ? g_n128 : g_n64;
    if ((int)blockIdx.y >= ntiles) return;
    const int4 tt     = (MT == 128) ? g_t128[blockIdx.y] : g_t64[blockIdx.y];
    const int  e      = tt.x;
    const int  row0   = tt.y;
    const int  rowend = tt.z;

    extern __shared__ __align__(1024) char smem[];
    __shared__ int rm[MT];
    const uint32_t sb = smem_to_u32(smem);
    const int tid = threadIdx.x;
    const int wid = tid >> 5;
    const int lid = tid & 31;
    const int wm  = wid % MWARPS;
    const int wn  = wid / MWARPS;
    const int n0  = blockIdx.x * 128;

    if (tid < MT) {
        const int r = row0 + tid;
        rm[tid] = (r < rowend) ? g_rowmap[r] : -1;
    }
    __syncthreads();

    const __half* aSrc[2] = {Ah, Al};
    const int nst = K >> 6;

    auto load_stage = [&](int s) {
        const int k0 = s << 6;
        const uint32_t tb = sb + (uint32_t)(s & 1) * STAGE;
#pragma unroll
        for (int it = 0; it < ITERS; it++) {
            int slot = it * 256 + tid;
            if (slot < A_SLOTS) {        // A hi/lo
                int arr = slot >= MT * 8;
                int idx = slot - arr * (MT * 8);
                int r   = idx >> 3;
                int c   = idx & 7;
                const __half* src;
                uint32_t sz;
                if (SOFTSIGN) {
                    int sr = rm[r];
                    src = aSrc[arr] + (size_t)(sr < 0 ? 0 : sr) * K + k0 + c * 8;
                    sz  = (sr < 0) ? 0u : 16u;
                } else {
                    src = aSrc[arr] + (size_t)(row0 + r) * K + k0 + c * 8;
                    sz  = 16u;
                }
                uint32_t dst = tb + (arr ? OFF_AL : 0u) +
                               SWZ128((uint32_t)(r * 128 + c * 16));
                cp16(dst, src, sz);
            } else {                     // B
                int idx = slot - A_SLOTS;
                int r   = idx >> 3;
                int c   = idx & 7;
                const __half* src =
                    Bw + ((size_t)e * Ntot + n0 + r) * K + k0 + c * 8;
                uint32_t dst = tb + OFF_B + SWZ128((uint32_t)(r * 128 + c * 16));
                cp16(dst, src, 16u);
            }
        }
        CP_COMMIT();
    };

    float acc[2][NT8][4];
#pragma unroll
    for (int mt = 0; mt < 2; mt++)
#pragma unroll
        for (int nt = 0; nt < NT8; nt++)
#pragma unroll
            for (int q = 0; q < 4; q++) acc[mt][nt][q] = 0.0f;

    load_stage(0);
    load_stage(1);

    for (int s = 0; s < nst; s++) {
        CP_WAIT1();
        __syncthreads();
        const uint32_t base = sb + (uint32_t)(s & 1) * STAGE;

#pragma unroll
        for (int kk = 0; kk < 4; kk++) {
            const uint32_t cb = (uint32_t)(kk * 32 + ((lid >> 4) << 4));
            uint32_t ah[2][4], al[2][4];
#pragma unroll
            for (int mt = 0; mt < 2; mt++) {
                const uint32_t off =
                    SWZ128((uint32_t)((wm * 32 + mt * 16 + (lid & 15)) * 128) + cb);
                ldsm4(ah[mt], base + off);
                ldsm4(al[mt], base + OFF_AL + off);
            }
#pragma unroll
            for (int np = 0; np < NP; np++) {
                const uint32_t off =
                    SWZ128((uint32_t)((wn * WARP_N + np * 16 + (lid & 15)) * 128) + cb);
                uint32_t bh[4];
                ldsm4(bh, base + OFF_B + off);
                const int nt0 = np * 2;
#pragma unroll
                for (int q = 0; q < 2; q++) {
                    mma16816(acc[0][nt0 + q], ah[0], bh[q], bh[2 + q]);
                    mma16816(acc[1][nt0 + q], ah[1], bh[q], bh[2 + q]);
                }
#pragma unroll
                for (int q = 0; q < 2; q++) {
                    mma16816(acc[0][nt0 + q], al[0], bh[q], bh[2 + q]);
                    mma16816(acc[1][nt0 + q], al[1], bh[q], bh[2 + q]);
                }
            }
        }
        __syncthreads();
        if (s + 2 < nst) load_stage(s + 2);
        else CP_COMMIT();
    }

    // ---------------- epilogue ----------------
    const int gq = lid >> 2;
    const int rq = lid & 3;
    float2 bv[NT8];
#pragma unroll
    for (int nt = 0; nt < NT8; nt++) {
        const int col = n0 + wn * WARP_N + nt * 8 + rq * 2;
        bv[nt] = *reinterpret_cast<const float2*>(bias + (size_t)e * Ntot + col);
    }

#pragma unroll
    for (int mt = 0; mt < 2; mt++) {
#pragma unroll
        for (int nt = 0; nt < NT8; nt++) {
            const int lr0 = wm * 32 + mt * 16 + gq;
            const int col = n0 + wn * WARP_N + nt * 8 + rq * 2;
            float c0 = acc[mt][nt][0] + bv[nt].x;
            float c1 = acc[mt][nt][1] + bv[nt].y;
            float c2 = acc[mt][nt][2] + bv[nt].x;
            float c3 = acc[mt][nt][3] + bv[nt].y;
            if (SOFTSIGN) {
                c0 = c0 / (1.0f + fabsf(c0));
                c1 = c1 / (1.0f + fabsf(c1));
                c2 = c2 / (1.0f + fabsf(c2));
                c3 = c3 / (1.0f + fabsf(c3));
                __half h0 = __float2half_rn(c0), h1 = __float2half_rn(c1);
                __half h2 = __float2half_rn(c2), h3 = __float2half_rn(c3);
                __half l0 = __float2half_rn(c0 - __half2float(h0));
                __half l1 = __float2half_rn(c1 - __half2float(h1));
                __half l2 = __float2half_rn(c2 - __half2float(h2));
                __half l3 = __float2half_rn(c3 - __half2float(h3));
                if (row0 + lr0 < rowend) {
                    size_t o0 = (size_t)(row0 + lr0) * Ntot + col;
                    *reinterpret_cast<__half2*>(outH + o0) = __half2(h0, h1);
                    *reinterpret_cast<__half2*>(outL + o0) = __half2(l0, l1);
                }
                if (row0 + lr0 + 8 < rowend) {
                    size_t o1 = (size_t)(row0 + lr0 + 8) * Ntot + col;
                    *reinterpret_cast<__half2*>(outH + o1) = __half2(h2, h3);
                    *reinterpret_cast<__half2*>(outL + o1) = __half2(l2, l3);
                }
            } else {
                const int d0 = rm[lr0];
                const int d1 = rm[lr0 + 8];
                if (d0 >= 0)
                    *reinterpret_cast<float2*>(outF + (size_t)d0 * Ntot + col) =
                        make_float2(c0, c1);
                if (d1 >= 0)
                    *reinterpret_cast<float2*>(outF + (size_t)d1 * Ntot + col) =
                        make_float2(c2, c3);
            }
        }
    }
}

// ---------------- host launcher ----------------
extern "C" void kernel_launch(void* const* d_in, const int* in_sizes, int n_in,
                              void* d_out, int out_size)
{
    const float* x   = (const float*)d_in[0];
    const int*   eid = (const int*)d_in[1];
    const float* W1  = (const float*)d_in[2];
    const float* b1  = (const float*)d_in[3];
    const float* W2  = (const float*)d_in[4];
    const float* b2  = (const float*)d_in[5];
    float* out = (float*)d_out;

    __half *xh, *xl, *w1, *w2, *ah, *al;
    cudaGetSymbolAddress((void**)&xh, g_xh);
    cudaGetSymbolAddress((void**)&xl, g_xl);
    cudaGetSymbolAddress((void**)&w1, g_w1);
    cudaGetSymbolAddress((void**)&w2, g_w2);
    cudaGetSymbolAddress((void**)&ah, g_ah);
    cudaGetSymbolAddress((void**)&al, g_al);

    constexpr int SMEM1 = 2 * (128 * 256 + 16384);  // 98304
    constexpr int SMEM2 = 2 * (64 * 256 + 16384);   // 65536
    cudaFuncSetAttribute(mma_gemm<128, true>,
                         cudaFuncAttributeMaxDynamicSharedMemorySize, SMEM1);
    cudaFuncSetAttribute(mma_gemm<64, false>,
                         cudaFuncAttributeMaxDynamicSharedMemorySize, SMEM2);

    // 1) expert sort / tile tables / rowmap
    prep_kernel<<<1, 256>>>(eid);
    // 2) x -> fp16 hi/lo
    {
        int n4 = (TOTAL_ROWS * N_IN) / 4;
        convert_x_kernel<<<(n4 + 255) / 256, 256>>>(x, xh, xl, n4);
    }
    // 3) weights -> fp16 transposed (vectorized stores)
    convert_w_kernel<<<dim3(H_MID / 32, N_IN / 64, E_NUM), 256>>>(W1, w1, N_IN, H_MID);
    convert_w_kernel<<<dim3(P_OUT / 32, H_MID / 64, E_NUM), 256>>>(W2, w2, H_MID, P_OUT);
    // 4) GEMM1: M128xN128 tiles, 2 CTA/SM
    mma_gemm<128, true><<<dim3(H_MID / 128, MAXT128), 256, SMEM1>>>(
        xh, xl, w1, b1, nullptr, ah, al, /*K=*/N_IN, /*Ntot=*/H_MID);
    // 5) GEMM2: M64xN128 tiles, 2 CTA/SM
    mma_gemm<64, false><<<dim3(P_OUT / 128, MAXT64), 256, SMEM2>>>(
        ah, al, w2, b2, out, nullptr, nullptr, /*K=*/H_MID, /*Ntot=*/P_OUT);
}

// round 9
// speedup vs baseline: 5.6002x; 1.4816x over previous
#include <cuda_runtime.h>
#include <cuda_fp16.h>
#include <cstdint>

// Problem constants: E=8, N=512(K1), H=1024, P=512, F=100, B=128
#define E_NUM    8
#define B_TRIALS 128
#define F_BINS   100
#define N_IN     512
#define H_MID    1024
#define P_OUT    512
#define TOTAL_ROWS (B_TRIALS * F_BINS)   // 12800 packed rows
#define ACT_ROWS   13056                  // padded
#define MAXT128  120
#define MAXT64   224

// ---------------- device scratch ----------------
__device__ __half g_x[(size_t)TOTAL_ROWS * N_IN];
__device__ __half g_w1[(size_t)E_NUM * H_MID * N_IN];   // [E, N(out), K] K-major fp16
__device__ __half g_w2[(size_t)E_NUM * P_OUT * H_MID];
__device__ __half g_a[(size_t)ACT_ROWS * H_MID];        // act fp16, packed

__device__ int  g_order[B_TRIALS];
__device__ int  g_rowmap[TOTAL_ROWS];
__device__ int4 g_t128[MAXT128];
__device__ int  g_n128;
__device__ int4 g_t64[MAXT64];
__device__ int  g_n64;

// ---------------- low-level helpers ----------------
__device__ __forceinline__ uint32_t smem_to_u32(const void* p) {
    uint32_t a;
    asm("{ .reg .u64 t; cvta.to.shared.u64 t, %1; cvt.u32.u64 %0, t; }"
        : "=r"(a) : "l"(p));
    return a;
}
#define SWZ128(o) ((o) ^ (((o) >> 3) & 0x70))

__device__ __forceinline__ void cp16(uint32_t dst, const void* src, uint32_t src_sz) {
    asm volatile("cp.async.cg.shared.global [%0], [%1], 16, %2;"
                 :: "r"(dst), "l"(src), "r"(src_sz) : "memory");
}
#define CP_COMMIT() asm volatile("cp.async.commit_group;" ::: "memory")
#define CP_WAIT2()  asm volatile("cp.async.wait_group 2;" ::: "memory")

__device__ __forceinline__ void ldsm4(uint32_t* r, uint32_t addr) {
    asm volatile("ldmatrix.sync.aligned.m8n8.x4.shared.b16 {%0,%1,%2,%3}, [%4];"
                 : "=r"(r[0]), "=r"(r[1]), "=r"(r[2]), "=r"(r[3]) : "r"(addr));
}
__device__ __forceinline__ void mma16816(float* c, const uint32_t* a,
                                         uint32_t b0, uint32_t b1) {
    asm volatile(
        "mma.sync.aligned.m16n8k16.row.col.f32.f16.f16.f32 "
        "{%0,%1,%2,%3}, {%4,%5,%6,%7}, {%8,%9}, {%0,%1,%2,%3};"
        : "+f"(c[0]), "+f"(c[1]), "+f"(c[2]), "+f"(c[3])
        : "r"(a[0]), "r"(a[1]), "r"(a[2]), "r"(a[3]), "r"(b0), "r"(b1));
}

// ---------------- prep kernel ----------------
__global__ void prep_kernel(const int* __restrict__ eid) {
    __shared__ int cnt[E_NUM], off[E_NUM];
    const int tid = threadIdx.x;
    if (tid < E_NUM) cnt[tid] = 0;
    __syncthreads();
    if (tid < B_TRIALS) atomicAdd(&cnt[eid[tid]], 1);
    __syncthreads();
    if (tid == 0) {
        int o = 0;
        for (int g = 0; g < E_NUM; g++) { off[g] = o; o += cnt[g]; }
        int c[E_NUM];
        for (int g = 0; g < E_NUM; g++) c[g] = 0;
        for (int i = 0; i < B_TRIALS; i++) {
            int g = eid[i];
            g_order[off[g] + c[g]++] = i;
        }
        int t = 0;
        for (int g = 0; g < E_NUM; g++) {
            int r0 = off[g] * F_BINS;
            int r1 = (off[g] + cnt[g]) * F_BINS;
            for (int r = r0; r < r1; r += 128)
                g_t128[t++] = make_int4(g, r, r1, 0);
        }
        g_n128 = t;
        for (; t < MAXT128; t++) g_t128[t] = make_int4(0, 0, 0, 0);
        t = 0;
        for (int g = 0; g < E_NUM; g++) {
            int r0 = off[g] * F_BINS;
            int r1 = (off[g] + cnt[g]) * F_BINS;
            for (int r = r0; r < r1; r += 64)
                g_t64[t++] = make_int4(g, r, r1, 0);
        }
        g_n64 = t;
        for (; t < MAXT64; t++) g_t64[t] = make_int4(0, 0, 0, 0);
    }
    __syncthreads();
    for (int j = tid; j < TOTAL_ROWS; j += blockDim.x)
        g_rowmap[j] = g_order[j / F_BINS] * F_BINS + (j % F_BINS);
}

// ---------------- conversion kernels ----------------
__global__ void convert_x_kernel(const float* __restrict__ x,
                                 __half* __restrict__ xo, int n4) {
    int i = blockIdx.x * blockDim.x + threadIdx.x;
    if (i >= n4) return;
    float4 v = reinterpret_cast<const float4*>(x)[i];
    __half hb[4];
    hb[0] = __float2half_rn(v.x);
    hb[1] = __float2half_rn(v.y);
    hb[2] = __float2half_rn(v.z);
    hb[3] = __float2half_rn(v.w);
    reinterpret_cast<uint2*>(xo)[i] = *reinterpret_cast<uint2*>(hb);
}

// W [E,K,Nt] fp32 -> Wt [E,Nt,K] fp16, 16B vectorized stores.
// tile: 64 k-rows x 32 n-cols, 256 threads.
__global__ void convert_w_kernel(const float* __restrict__ W,
                                 __half* __restrict__ Wt, int K, int Nt) {
    __shared__ float t[64][33];
    int e  = blockIdx.z;
    int n0 = blockIdx.x * 32;
    int k0 = blockIdx.y * 64;
    const float* src = W + ((size_t)e * K + k0) * Nt + n0;
#pragma unroll
    for (int i = 0; i < 8; i++) {
        int r = (threadIdx.x >> 5) + i * 8;
        int c = threadIdx.x & 31;
        t[r][c] = src[(size_t)r * Nt + c];
    }
    __syncthreads();
    int n  = threadIdx.x >> 3;
    int kc = threadIdx.x & 7;
    __half h[8];
#pragma unroll
    for (int j = 0; j < 8; j++) h[j] = __float2half_rn(t[kc * 8 + j][n]);
    *reinterpret_cast<uint4*>(Wt + ((size_t)e * Nt + n0 + n) * K + k0 + kc * 8) =
        *reinterpret_cast<uint4*>(h);
}

// ---------------- grouped single-term fp16 mma.sync GEMM ----------------
// MT in {128, 64}; N tile 128; 256 threads (8 warps); 2 CTAs/SM; 3-stage pipeline.
template <int MT, bool SOFTSIGN>
__global__ __launch_bounds__(256, 2)
void mma_gemm(const __half* __restrict__ Aw,
              const __half* __restrict__ Bw,
              const float* __restrict__ bias,
              float* __restrict__ outF,
              __half* __restrict__ outH,
              int K, int Ntot)
{
    constexpr int MWARPS = MT / 32;            // 4 or 2
    constexpr int NWARPS = 8 / MWARPS;         // 2 or 4
    constexpr int WARP_N = 128 / NWARPS;       // 64 or 32
    constexpr int NP     = WARP_N / 16;        // 4 or 2
    constexpr int NT8    = WARP_N / 8;         // 8 or 4
    constexpr uint32_t OFF_B = MT * 128;
    constexpr uint32_t STAGE = MT * 128 + 16384;
    constexpr int A_SLOTS = MT * 8;
    constexpr int SLOTS   = A_SLOTS + 1024;    // + B (128 rows x 8 chunks)
    constexpr int ITERS   = SLOTS / 256;

    const int ntiles = (MT == 128) ? g_n128 : g_n64;
    if ((int)blockIdx.y >= ntiles) return;
    const int4 tt     = (MT == 128) ? g_t128[blockIdx.y] : g_t64[blockIdx.y];
    const int  e      = tt.x;
    const int  row0   = tt.y;
    const int  rowend = tt.z;

    extern __shared__ __align__(1024) char smem[];
    __shared__ int rm[MT];
    const uint32_t sb = smem_to_u32(smem);
    const int tid = threadIdx.x;
    const int wid = tid >> 5;
    const int lid = tid & 31;
    const int wm  = wid % MWARPS;
    const int wn  = wid / MWARPS;
    const int n0  = blockIdx.x * 128;

    if (tid < MT) {
        const int r = row0 + tid;
        rm[tid] = (r < rowend) ? g_rowmap[r] : -1;
    }
    __syncthreads();

    const int nst = K >> 6;

    auto load_stage = [&](int s) {
        const int k0 = s << 6;
        const uint32_t tb = sb + (uint32_t)(s % 3) * STAGE;
#pragma unroll
        for (int it = 0; it < ITERS; it++) {
            int slot = it * 256 + tid;
            if (slot < A_SLOTS) {        // A
                int r = slot >> 3;
                int c = slot & 7;
                const __half* src;
                uint32_t sz;
                if (SOFTSIGN) {
                    int sr = rm[r];
                    src = Aw + (size_t)(sr < 0 ? 0 : sr) * K + k0 + c * 8;
                    sz  = (sr < 0) ? 0u : 16u;
                } else {
                    src = Aw + (size_t)(row0 + r) * K + k0 + c * 8;
                    sz  = 16u;
                }
                uint32_t dst = tb + SWZ128((uint32_t)(r * 128 + c * 16));
                cp16(dst, src, sz);
            } else {                     // B
                int idx = slot - A_SLOTS;
                int r   = idx >> 3;
                int c   = idx & 7;
                const __half* src =
                    Bw + ((size_t)e * Ntot + n0 + r) * K + k0 + c * 8;
                uint32_t dst = tb + OFF_B + SWZ128((uint32_t)(r * 128 + c * 16));
                cp16(dst, src, 16u);
            }
        }
        CP_COMMIT();
    };

    float acc[2][NT8][4];
#pragma unroll
    for (int mt = 0; mt < 2; mt++)
#pragma unroll
        for (int nt = 0; nt < NT8; nt++)
#pragma unroll
            for (int q = 0; q < 4; q++) acc[mt][nt][q] = 0.0f;

    load_stage(0);
    load_stage(1);
    load_stage(2);

    for (int s = 0; s < nst; s++) {
        CP_WAIT2();
        __syncthreads();
        const uint32_t base = sb + (uint32_t)(s % 3) * STAGE;

#pragma unroll
        for (int kk = 0; kk < 4; kk++) {
            const uint32_t cb = (uint32_t)(kk * 32 + ((lid >> 4) << 4));
            uint32_t ah[2][4];
#pragma unroll
            for (int mt = 0; mt < 2; mt++) {
                const uint32_t off =
                    SWZ128((uint32_t)((wm * 32 + mt * 16 + (lid & 15)) * 128) + cb);
                ldsm4(ah[mt], base + off);
            }
#pragma unroll
            for (int np = 0; np < NP; np++) {
                const uint32_t off =
                    SWZ128((uint32_t)((wn * WARP_N + np * 16 + (lid & 15)) * 128) + cb);
                uint32_t bh[4];
                ldsm4(bh, base + OFF_B + off);
                const int nt0 = np * 2;
#pragma unroll
                for (int q = 0; q < 2; q++) {
                    mma16816(acc[0][nt0 + q], ah[0], bh[q], bh[2 + q]);
                    mma16816(acc[1][nt0 + q], ah[1], bh[q], bh[2 + q]);
                }
            }
        }
        __syncthreads();
        if (s + 3 < nst) load_stage(s + 3);
        else CP_COMMIT();
    }

    // ---------------- epilogue ----------------
    const int gq = lid >> 2;
    const int rq = lid & 3;
    float2 bv[NT8];
#pragma unroll
    for (int nt = 0; nt < NT8; nt++) {
        const int col = n0 + wn * WARP_N + nt * 8 + rq * 2;
        bv[nt] = *reinterpret_cast<const float2*>(bias + (size_t)e * Ntot + col);
    }

#pragma unroll
    for (int mt = 0; mt < 2; mt++) {
#pragma unroll
        for (int nt = 0; nt < NT8; nt++) {
            const int lr0 = wm * 32 + mt * 16 + gq;
            const int col = n0 + wn * WARP_N + nt * 8 + rq * 2;
            float c0 = acc[mt][nt][0] + bv[nt].x;
            float c1 = acc[mt][nt][1] + bv[nt].y;
            float c2 = acc[mt][nt][2] + bv[nt].x;
            float c3 = acc[mt][nt][3] + bv[nt].y;
            if (SOFTSIGN) {
                c0 = c0 / (1.0f + fabsf(c0));
                c1 = c1 / (1.0f + fabsf(c1));
                c2 = c2 / (1.0f + fabsf(c2));
                c3 = c3 / (1.0f + fabsf(c3));
                __half h0 = __float2half_rn(c0), h1 = __float2half_rn(c1);
                __half h2 = __float2half_rn(c2), h3 = __float2half_rn(c3);
                if (row0 + lr0 < rowend) {
                    size_t o0 = (size_t)(row0 + lr0) * Ntot + col;
                    *reinterpret_cast<__half2*>(outH + o0) = __half2(h0, h1);
                }
                if (row0 + lr0 + 8 < rowend) {
                    size_t o1 = (size_t)(row0 + lr0 + 8) * Ntot + col;
                    *reinterpret_cast<__half2*>(outH + o1) = __half2(h2, h3);
                }
            } else {
                const int d0 = rm[lr0];
                const int d1 = rm[lr0 + 8];
                if (d0 >= 0)
                    *reinterpret_cast<float2*>(outF + (size_t)d0 * Ntot + col) =
                        make_float2(c0, c1);
                if (d1 >= 0)
                    *reinterpret_cast<float2*>(outF + (size_t)d1 * Ntot + col) =
                        make_float2(c2, c3);
            }
        }
    }
}

// ---------------- host launcher ----------------
extern "C" void kernel_launch(void* const* d_in, const int* in_sizes, int n_in,
                              void* d_out, int out_size)
{
    const float* x   = (const float*)d_in[0];
    const int*   eid = (const int*)d_in[1];
    const float* W1  = (const float*)d_in[2];
    const float* b1  = (const float*)d_in[3];
    const float* W2  = (const float*)d_in[4];
    const float* b2  = (const float*)d_in[5];
    float* out = (float*)d_out;

    __half *xv, *w1, *w2, *av;
    cudaGetSymbolAddress((void**)&xv, g_x);
    cudaGetSymbolAddress((void**)&w1, g_w1);
    cudaGetSymbolAddress((void**)&w2, g_w2);
    cudaGetSymbolAddress((void**)&av, g_a);

    constexpr int SMEM1 = 3 * (128 * 128 + 16384);  // 98304
    constexpr int SMEM2 = 3 * (64 * 128 + 16384);   // 73728
    cudaFuncSetAttribute(mma_gemm<128, true>,
                         cudaFuncAttributeMaxDynamicSharedMemorySize, SMEM1);
    cudaFuncSetAttribute(mma_gemm<64, false>,
                         cudaFuncAttributeMaxDynamicSharedMemorySize, SMEM2);

    // 1) expert sort / tile tables / rowmap
    prep_kernel<<<1, 256>>>(eid);
    // 2) x -> fp16
    {
        int n4 = (TOTAL_ROWS * N_IN) / 4;
        convert_x_kernel<<<(n4 + 255) / 256, 256>>>(x, xv, n4);
    }
    // 3) weights -> fp16 transposed
    convert_w_kernel<<<dim3(H_MID / 32, N_IN / 64, E_NUM), 256>>>(W1, w1, N_IN, H_MID);
    convert_w_kernel<<<dim3(P_OUT / 32, H_MID / 64, E_NUM), 256>>>(W2, w2, H_MID, P_OUT);
    // 4) GEMM1: M128xN128 tiles
    mma_gemm<128, true><<<dim3(H_MID / 128, MAXT128), 256, SMEM1>>>(
        xv, w1, b1, nullptr, av, /*K=*/N_IN, /*Ntot=*/H_MID);
    // 5) GEMM2: M64xN128 tiles
    mma_gemm<64, false><<<dim3(P_OUT / 128, MAXT64), 256, SMEM2>>>(
        av, w2, b2, out, nullptr, /*K=*/H_MID, /*Ntot=*/P_OUT);
}

// round 10
// speedup vs baseline: 5.8477x; 1.0442x over previous
#include <cuda_runtime.h>
#include <cuda_fp16.h>
#include <cstdint>

// Problem constants: E=8, N=512(K1), H=1024, P=512, F=100, B=128
#define E_NUM    8
#define B_TRIALS 128
#define F_BINS   100
#define N_IN     512
#define H_MID    1024
#define P_OUT    512
#define TOTAL_ROWS (B_TRIALS * F_BINS)   // 12800 packed rows
#define ACT_ROWS   13056                  // padded
#define MAXT128  120
#define MAXT64   224

// ---------------- device scratch ----------------
__device__ __half g_x[(size_t)TOTAL_ROWS * N_IN];
__device__ __half g_w1[(size_t)E_NUM * H_MID * N_IN];   // [E, N(out), K] K-major fp16
__device__ __half g_w2[(size_t)E_NUM * P_OUT * H_MID];
__device__ __half g_a[(size_t)ACT_ROWS * H_MID];        // act fp16, packed

__device__ int  g_order[B_TRIALS];
__device__ int  g_rowmap[TOTAL_ROWS];
__device__ int4 g_t128[MAXT128];
__device__ int  g_n128;
__device__ int4 g_t64[MAXT64];
__device__ int  g_n64;

// ---------------- low-level helpers ----------------
__device__ __forceinline__ uint32_t smem_to_u32(const void* p) {
    uint32_t a;
    asm("{ .reg .u64 t; cvta.to.shared.u64 t, %1; cvt.u32.u64 %0, t; }"
        : "=r"(a) : "l"(p));
    return a;
}
#define SWZ128(o) ((o) ^ (((o) >> 3) & 0x70))

__device__ __forceinline__ void cp16(uint32_t dst, const void* src, uint32_t src_sz) {
    asm volatile("cp.async.cg.shared.global [%0], [%1], 16, %2;"
                 :: "r"(dst), "l"(src), "r"(src_sz) : "memory");
}
#define CP_COMMIT() asm volatile("cp.async.commit_group;" ::: "memory")
#define CP_WAIT1()  asm volatile("cp.async.wait_group 1;" ::: "memory")

__device__ __forceinline__ void ldsm4(uint32_t* r, uint32_t addr) {
    asm volatile("ldmatrix.sync.aligned.m8n8.x4.shared.b16 {%0,%1,%2,%3}, [%4];"
                 : "=r"(r[0]), "=r"(r[1]), "=r"(r[2]), "=r"(r[3]) : "r"(addr));
}
__device__ __forceinline__ void mma16816(float* c, const uint32_t* a,
                                         uint32_t b0, uint32_t b1) {
    asm volatile(
        "mma.sync.aligned.m16n8k16.row.col.f32.f16.f16.f32 "
        "{%0,%1,%2,%3}, {%4,%5,%6,%7}, {%8,%9}, {%0,%1,%2,%3};"
        : "+f"(c[0]), "+f"(c[1]), "+f"(c[2]), "+f"(c[3])
        : "r"(a[0]), "r"(a[1]), "r"(a[2]), "r"(a[3]), "r"(b0), "r"(b1));
}

// ---------------- prep kernel ----------------
__global__ void prep_kernel(const int* __restrict__ eid) {
    __shared__ int cnt[E_NUM], off[E_NUM];
    const int tid = threadIdx.x;
    if (tid < E_NUM) cnt[tid] = 0;
    __syncthreads();
    if (tid < B_TRIALS) atomicAdd(&cnt[eid[tid]], 1);
    __syncthreads();
    if (tid == 0) {
        int o = 0;
        for (int g = 0; g < E_NUM; g++) { off[g] = o; o += cnt[g]; }
        int c[E_NUM];
        for (int g = 0; g < E_NUM; g++) c[g] = 0;
        for (int i = 0; i < B_TRIALS; i++) {
            int g = eid[i];
            g_order[off[g] + c[g]++] = i;
        }
        int t = 0;
        for (int g = 0; g < E_NUM; g++) {
            int r0 = off[g] * F_BINS;
            int r1 = (off[g] + cnt[g]) * F_BINS;
            for (int r = r0; r < r1; r += 128)
                g_t128[t++] = make_int4(g, r, r1, 0);
        }
        g_n128 = t;
        for (; t < MAXT128; t++) g_t128[t] = make_int4(0, 0, 0, 0);
        t = 0;
        for (int g = 0; g < E_NUM; g++) {
            int r0 = off[g] * F_BINS;
            int r1 = (off[g] + cnt[g]) * F_BINS;
            for (int r = r0; r < r1; r += 64)
                g_t64[t++] = make_int4(g, r, r1, 0);
        }
        g_n64 = t;
        for (; t < MAXT64; t++) g_t64[t] = make_int4(0, 0, 0, 0);
    }
    __syncthreads();
    for (int j = tid; j < TOTAL_ROWS; j += blockDim.x)
        g_rowmap[j] = g_order[j / F_BINS] * F_BINS + (j % F_BINS);
}

// ---------------- merged conversion kernel ----------------
// W transpose tile as device fn: 64 k-rows x 32 n-cols, 256 threads
__device__ __forceinline__ void conv_w_tile(const float* __restrict__ W,
                                            __half* __restrict__ Wt,
                                            int K, int Nt, int bx, int by, int e) {
    __shared__ float t[64][33];
    int n0 = bx * 32;
    int k0 = by * 64;
    const float* src = W + ((size_t)e * K + k0) * Nt + n0;
#pragma unroll
    for (int i = 0; i < 8; i++) {
        int r = (threadIdx.x >> 5) + i * 8;
        int c = threadIdx.x & 31;
        t[r][c] = src[(size_t)r * Nt + c];
    }
    __syncthreads();
    int n  = threadIdx.x >> 3;
    int kc = threadIdx.x & 7;
    __half h[8];
#pragma unroll
    for (int j = 0; j < 8; j++) h[j] = __float2half_rn(t[kc * 8 + j][n]);
    *reinterpret_cast<uint4*>(Wt + ((size_t)e * Nt + n0 + n) * K + k0 + kc * 8) =
        *reinterpret_cast<uint4*>(h);
}

#define XBLOCKS  ((TOTAL_ROWS * N_IN) / 4 / 256)       // 6400
#define W1BLOCKS (((H_MID / 32) * (N_IN / 64)) * E_NUM)  // 2048
#define W2BLOCKS (((P_OUT / 32) * (H_MID / 64)) * E_NUM) // 2048

__global__ void convert_all_kernel(const float* __restrict__ x,
                                   const float* __restrict__ W1,
                                   const float* __restrict__ W2,
                                   __half* __restrict__ xo,
                                   __half* __restrict__ w1o,
                                   __half* __restrict__ w2o) {
    int b = blockIdx.x;
    if (b < XBLOCKS) {
        int i = b * 256 + threadIdx.x;
        float4 v = reinterpret_cast<const float4*>(x)[i];
        __half hb[4];
        hb[0] = __float2half_rn(v.x);
        hb[1] = __float2half_rn(v.y);
        hb[2] = __float2half_rn(v.z);
        hb[3] = __float2half_rn(v.w);
        reinterpret_cast<uint2*>(xo)[i] = *reinterpret_cast<uint2*>(hb);
    } else if (b < XBLOCKS + W1BLOCKS) {
        int idx = b - XBLOCKS;
        int bx = idx % (H_MID / 32);
        int by = (idx / (H_MID / 32)) % (N_IN / 64);
        int e  = idx / ((H_MID / 32) * (N_IN / 64));
        conv_w_tile(W1, w1o, N_IN, H_MID, bx, by, e);
    } else {
        int idx = b - XBLOCKS - W1BLOCKS;
        int bx = idx % (P_OUT / 32);
        int by = (idx / (P_OUT / 32)) % (H_MID / 64);
        int e  = idx / ((P_OUT / 32) * (H_MID / 64));
        conv_w_tile(W2, w2o, H_MID, P_OUT, bx, by, e);
    }
}

// ---------------- grouped single-term fp16 mma.sync GEMM ----------------
// MT in {128, 64}; N tile 128; 256 threads (8 warps); 2 CTAs/SM;
// 3 buffers, 2 in-flight cp.async groups, loads issued BEFORE compute,
// ONE __syncthreads per k-stage.
template <int MT, bool SOFTSIGN>
__global__ __launch_bounds__(256, 2)
void mma_gemm(const __half* __restrict__ Aw,
              const __half* __restrict__ Bw,
              const float* __restrict__ bias,
              float* __restrict__ outF,
              __half* __restrict__ outH,
              int K, int Ntot)
{
    constexpr int MWARPS = MT / 32;            // 4 or 2
    constexpr int NWARPS = 8 / MWARPS;         // 2 or 4
    constexpr int WARP_N = 128 / NWARPS;       // 64 or 32
    constexpr int NP     = WARP_N / 16;        // 4 or 2
    constexpr int NT8    = WARP_N / 8;         // 8 or 4
    constexpr uint32_t OFF_B = MT * 128;
    constexpr uint32_t STAGE = MT * 128 + 16384;
    constexpr int A_SLOTS = MT * 8;
    constexpr int SLOTS   = A_SLOTS + 1024;
    constexpr int ITERS   = SLOTS / 256;

    const int ntiles = (MT == 128) ? g_n128 : g_n64;
    if ((int)blockIdx.y >= ntiles) return;
    const int4 tt     = (MT == 128) ? g_t128[blockIdx.y] : g_t64[blockIdx.y];
    const int  e      = tt.x;
    const int  row0   = tt.y;
    const int  rowend = tt.z;

    extern __shared__ __align__(1024) char smem[];
    __shared__ int rm[MT];
    const uint32_t sb = smem_to_u32(smem);
    const int tid = threadIdx.x;
    const int wid = tid >> 5;
    const int lid = tid & 31;
    const int wm  = wid % MWARPS;
    const int wn  = wid / MWARPS;
    const int n0  = blockIdx.x * 128;

    if (tid < MT) {
        const int r = row0 + tid;
        rm[tid] = (r < rowend) ? g_rowmap[r] : -1;
    }
    __syncthreads();

    const int nst = K >> 6;

    auto load_stage = [&](int s) {
        const int k0 = s << 6;
        const uint32_t tb = sb + (uint32_t)(s % 3) * STAGE;
#pragma unroll
        for (int it = 0; it < ITERS; it++) {
            int slot = it * 256 + tid;
            if (slot < A_SLOTS) {        // A
                int r = slot >> 3;
                int c = slot & 7;
                const __half* src;
                uint32_t sz;
                if (SOFTSIGN) {
                    int sr = rm[r];
                    src = Aw + (size_t)(sr < 0 ? 0 : sr) * K + k0 + c * 8;
                    sz  = (sr < 0) ? 0u : 16u;
                } else {
                    src = Aw + (size_t)(row0 + r) * K + k0 + c * 8;
                    sz  = 16u;
                }
                uint32_t dst = tb + SWZ128((uint32_t)(r * 128 + c * 16));
                cp16(dst, src, sz);
            } else {                     // B
                int idx = slot - A_SLOTS;
                int r   = idx >> 3;
                int c   = idx & 7;
                const __half* src =
                    Bw + ((size_t)e * Ntot + n0 + r) * K + k0 + c * 8;
                uint32_t dst = tb + OFF_B + SWZ128((uint32_t)(r * 128 + c * 16));
                cp16(dst, src, 16u);
            }
        }
        CP_COMMIT();
    };

    float acc[2][NT8][4];
#pragma unroll
    for (int mt = 0; mt < 2; mt++)
#pragma unroll
        for (int nt = 0; nt < NT8; nt++)
#pragma unroll
            for (int q = 0; q < 4; q++) acc[mt][nt][q] = 0.0f;

    load_stage(0);
    load_stage(1);

    for (int s = 0; s < nst; s++) {
        CP_WAIT1();          // stage s resident (<=1 group outstanding)
        __syncthreads();     // all warps past compute(s-1); smem visible
        // issue next load into buffer (s+2)%3 == (s-1)%3, consumed at s-1
        if (s + 2 < nst) load_stage(s + 2);
        else CP_COMMIT();    // keep group accounting uniform for CP_WAIT1

        const uint32_t base = sb + (uint32_t)(s % 3) * STAGE;
#pragma unroll
        for (int kk = 0; kk < 4; kk++) {
            const uint32_t cb = (uint32_t)(kk * 32 + ((lid >> 4) << 4));
            uint32_t ah[2][4];
#pragma unroll
            for (int mt = 0; mt < 2; mt++) {
                const uint32_t off =
                    SWZ128((uint32_t)((wm * 32 + mt * 16 + (lid & 15)) * 128) + cb);
                ldsm4(ah[mt], base + off);
            }
#pragma unroll
            for (int np = 0; np < NP; np++) {
                const uint32_t off =
                    SWZ128((uint32_t)((wn * WARP_N + np * 16 + (lid & 15)) * 128) + cb);
                uint32_t bh[4];
                ldsm4(bh, base + OFF_B + off);
                const int nt0 = np * 2;
#pragma unroll
                for (int q = 0; q < 2; q++) {
                    mma16816(acc[0][nt0 + q], ah[0], bh[q], bh[2 + q]);
                    mma16816(acc[1][nt0 + q], ah[1], bh[q], bh[2 + q]);
                }
            }
        }
        // no trailing sync: next iteration's top sync protects buffer reuse
    }

    // ---------------- epilogue ----------------
    const int gq = lid >> 2;
    const int rq = lid & 3;
    float2 bv[NT8];
#pragma unroll
    for (int nt = 0; nt < NT8; nt++) {
        const int col = n0 + wn * WARP_N + nt * 8 + rq * 2;
        bv[nt] = *reinterpret_cast<const float2*>(bias + (size_t)e * Ntot + col);
    }

#pragma unroll
    for (int mt = 0; mt < 2; mt++) {
#pragma unroll
        for (int nt = 0; nt < NT8; nt++) {
            const int lr0 = wm * 32 + mt * 16 + gq;
            const int col = n0 + wn * WARP_N + nt * 8 + rq * 2;
            float c0 = acc[mt][nt][0] + bv[nt].x;
            float c1 = acc[mt][nt][1] + bv[nt].y;
            float c2 = acc[mt][nt][2] + bv[nt].x;
            float c3 = acc[mt][nt][3] + bv[nt].y;
            if (SOFTSIGN) {
                c0 = c0 / (1.0f + fabsf(c0));
                c1 = c1 / (1.0f + fabsf(c1));
                c2 = c2 / (1.0f + fabsf(c2));
                c3 = c3 / (1.0f + fabsf(c3));
                __half h0 = __float2half_rn(c0), h1 = __float2half_rn(c1);
                __half h2 = __float2half_rn(c2), h3 = __float2half_rn(c3);
                if (row0 + lr0 < rowend) {
                    size_t o0 = (size_t)(row0 + lr0) * Ntot + col;
                    *reinterpret_cast<__half2*>(outH + o0) = __half2(h0, h1);
                }
                if (row0 + lr0 + 8 < rowend) {
                    size_t o1 = (size_t)(row0 + lr0 + 8) * Ntot + col;
                    *reinterpret_cast<__half2*>(outH + o1) = __half2(h2, h3);
                }
            } else {
                const int d0 = rm[lr0];
                const int d1 = rm[lr0 + 8];
                if (d0 >= 0)
                    *reinterpret_cast<float2*>(outF + (size_t)d0 * Ntot + col) =
                        make_float2(c0, c1);
                if (d1 >= 0)
                    *reinterpret_cast<float2*>(outF + (size_t)d1 * Ntot + col) =
                        make_float2(c2, c3);
            }
        }
    }
}

// ---------------- host launcher ----------------
extern "C" void kernel_launch(void* const* d_in, const int* in_sizes, int n_in,
                              void* d_out, int out_size)
{
    const float* x   = (const float*)d_in[0];
    const int*   eid = (const int*)d_in[1];
    const float* W1  = (const float*)d_in[2];
    const float* b1  = (const float*)d_in[3];
    const float* W2  = (const float*)d_in[4];
    const float* b2  = (const float*)d_in[5];
    float* out = (float*)d_out;

    __half *xv, *w1, *w2, *av;
    cudaGetSymbolAddress((void**)&xv, g_x);
    cudaGetSymbolAddress((void**)&w1, g_w1);
    cudaGetSymbolAddress((void**)&w2, g_w2);
    cudaGetSymbolAddress((void**)&av, g_a);

    constexpr int SMEM1 = 3 * (128 * 128 + 16384);  // 98304
    constexpr int SMEM2 = 3 * (64 * 128 + 16384);   // 73728
    cudaFuncSetAttribute(mma_gemm<128, true>,
                         cudaFuncAttributeMaxDynamicSharedMemorySize, SMEM1);
    cudaFuncSetAttribute(mma_gemm<64, false>,
                         cudaFuncAttributeMaxDynamicSharedMemorySize, SMEM2);

    // 1) expert sort / tile tables / rowmap
    prep_kernel<<<1, 256>>>(eid);
    // 2) all conversions in one launch
    convert_all_kernel<<<XBLOCKS + W1BLOCKS + W2BLOCKS, 256>>>(x, W1, W2, xv, w1, w2);
    // 3) GEMM1: M128xN128 tiles
    mma_gemm<128, true><<<dim3(H_MID / 128, MAXT128), 256, SMEM1>>>(
        xv, w1, b1, nullptr, av, /*K=*/N_IN, /*Ntot=*/H_MID);
    // 4) GEMM2: M64xN128 tiles
    mma_gemm<64, false><<<dim3(P_OUT / 128, MAXT64), 256, SMEM2>>>(
        av, w2, b2, out, nullptr, /*K=*/H_MID, /*Ntot=*/P_OUT);
}

// round 11
// speedup vs baseline: 6.2422x; 1.0675x over previous
#include <cuda_runtime.h>
#include <cuda_fp16.h>
#include <cstdint>

// Problem constants: E=8, N=512(K1), H=1024, P=512, F=100, B=128
#define E_NUM    8
#define B_TRIALS 128
#define F_BINS   100
#define N_IN     512
#define H_MID    1024
#define P_OUT    512
#define TOTAL_ROWS (B_TRIALS * F_BINS)   // 12800 packed rows
#define ACT_ROWS   13056                  // padded
#define MAXT128  120
#define MAXT64   224

// ---------------- device scratch ----------------
__device__ __half g_x[(size_t)TOTAL_ROWS * N_IN];
__device__ __half g_w1[(size_t)E_NUM * H_MID * N_IN];   // [E, N(out), K] K-major fp16
__device__ __half g_w2[(size_t)E_NUM * P_OUT * H_MID];
__device__ __half g_a[(size_t)ACT_ROWS * H_MID];        // act fp16, packed

__device__ int  g_order[B_TRIALS];
__device__ int  g_rowmap[TOTAL_ROWS];
__device__ int4 g_t128[MAXT128];
__device__ int  g_n128;
__device__ int4 g_t64[MAXT64];
__device__ int  g_n64;

// ---------------- low-level helpers ----------------
__device__ __forceinline__ uint32_t smem_to_u32(const void* p) {
    uint32_t a;
    asm("{ .reg .u64 t; cvta.to.shared.u64 t, %1; cvt.u32.u64 %0, t; }"
        : "=r"(a) : "l"(p));
    return a;
}
#define SWZ128(o) ((o) ^ (((o) >> 3) & 0x70))

__device__ __forceinline__ void cp16(uint32_t dst, const void* src) {
    asm volatile("cp.async.cg.shared.global [%0], [%1], 16;"
                 :: "r"(dst), "l"(src) : "memory");
}
#define CP_COMMIT() asm volatile("cp.async.commit_group;" ::: "memory")
#define CP_WAIT1()  asm volatile("cp.async.wait_group 1;" ::: "memory")

__device__ __forceinline__ void ldsm4(uint32_t* r, uint32_t addr) {
    asm volatile("ldmatrix.sync.aligned.m8n8.x4.shared.b16 {%0,%1,%2,%3}, [%4];"
                 : "=r"(r[0]), "=r"(r[1]), "=r"(r[2]), "=r"(r[3]) : "r"(addr));
}
__device__ __forceinline__ void mma16816(float* c, const uint32_t* a,
                                         uint32_t b0, uint32_t b1) {
    asm volatile(
        "mma.sync.aligned.m16n8k16.row.col.f32.f16.f16.f32 "
        "{%0,%1,%2,%3}, {%4,%5,%6,%7}, {%8,%9}, {%0,%1,%2,%3};"
        : "+f"(c[0]), "+f"(c[1]), "+f"(c[2]), "+f"(c[3])
        : "r"(a[0]), "r"(a[1]), "r"(a[2]), "r"(a[3]), "r"(b0), "r"(b1));
}

// ---------------- prep kernel ----------------
__global__ void prep_kernel(const int* __restrict__ eid) {
    __shared__ int cnt[E_NUM], off[E_NUM];
    const int tid = threadIdx.x;
    if (tid < E_NUM) cnt[tid] = 0;
    __syncthreads();
    if (tid < B_TRIALS) atomicAdd(&cnt[eid[tid]], 1);
    __syncthreads();
    if (tid == 0) {
        int o = 0;
        for (int g = 0; g < E_NUM; g++) { off[g] = o; o += cnt[g]; }
        int c[E_NUM];
        for (int g = 0; g < E_NUM; g++) c[g] = 0;
        for (int i = 0; i < B_TRIALS; i++) {
            int g = eid[i];
            g_order[off[g] + c[g]++] = i;
        }
        int t = 0;
        for (int g = 0; g < E_NUM; g++) {
            int r0 = off[g] * F_BINS;
            int r1 = (off[g] + cnt[g]) * F_BINS;
            for (int r = r0; r < r1; r += 128)
                g_t128[t++] = make_int4(g, r, r1, 0);
        }
        g_n128 = t;
        for (; t < MAXT128; t++) g_t128[t] = make_int4(0, 0, 0, 0);
        t = 0;
        for (int g = 0; g < E_NUM; g++) {
            int r0 = off[g] * F_BINS;
            int r1 = (off[g] + cnt[g]) * F_BINS;
            for (int r = r0; r < r1; r += 64)
                g_t64[t++] = make_int4(g, r, r1, 0);
        }
        g_n64 = t;
        for (; t < MAXT64; t++) g_t64[t] = make_int4(0, 0, 0, 0);
    }
    __syncthreads();
    for (int j = tid; j < TOTAL_ROWS; j += blockDim.x)
        g_rowmap[j] = g_order[j / F_BINS] * F_BINS + (j % F_BINS);
}

// ---------------- merged conversion kernel ----------------
__device__ __forceinline__ void conv_w_tile(const float* __restrict__ W,
                                            __half* __restrict__ Wt,
                                            int K, int Nt, int bx, int by, int e) {
    __shared__ float t[64][33];
    int n0 = bx * 32;
    int k0 = by * 64;
    const float* src = W + ((size_t)e * K + k0) * Nt + n0;
#pragma unroll
    for (int i = 0; i < 8; i++) {
        int r = (threadIdx.x >> 5) + i * 8;
        int c = threadIdx.x & 31;
        t[r][c] = src[(size_t)r * Nt + c];
    }
    __syncthreads();
    int n  = threadIdx.x >> 3;
    int kc = threadIdx.x & 7;
    __half h[8];
#pragma unroll
    for (int j = 0; j < 8; j++) h[j] = __float2half_rn(t[kc * 8 + j][n]);
    *reinterpret_cast<uint4*>(Wt + ((size_t)e * Nt + n0 + n) * K + k0 + kc * 8) =
        *reinterpret_cast<uint4*>(h);
}

#define XBLOCKS  ((TOTAL_ROWS * N_IN) / 4 / 256)        // 6400
#define W1BLOCKS (((H_MID / 32) * (N_IN / 64)) * E_NUM)  // 2048
#define W2BLOCKS (((P_OUT / 32) * (H_MID / 64)) * E_NUM) // 2048

__global__ void convert_all_kernel(const float* __restrict__ x,
                                   const float* __restrict__ W1,
                                   const float* __restrict__ W2,
                                   __half* __restrict__ xo,
                                   __half* __restrict__ w1o,
                                   __half* __restrict__ w2o) {
    int b = blockIdx.x;
    if (b < XBLOCKS) {
        int i = b * 256 + threadIdx.x;
        float4 v = reinterpret_cast<const float4*>(x)[i];
        __half hb[4];
        hb[0] = __float2half_rn(v.x);
        hb[1] = __float2half_rn(v.y);
        hb[2] = __float2half_rn(v.z);
        hb[3] = __float2half_rn(v.w);
        reinterpret_cast<uint2*>(xo)[i] = *reinterpret_cast<uint2*>(hb);
    } else if (b < XBLOCKS + W1BLOCKS) {
        int idx = b - XBLOCKS;
        int bx = idx % (H_MID / 32);
        int by = (idx / (H_MID / 32)) % (N_IN / 64);
        int e  = idx / ((H_MID / 32) * (N_IN / 64));
        conv_w_tile(W1, w1o, N_IN, H_MID, bx, by, e);
    } else {
        int idx = b - XBLOCKS - W1BLOCKS;
        int bx = idx % (P_OUT / 32);
        int by = (idx / (P_OUT / 32)) % (H_MID / 64);
        int e  = idx / ((P_OUT / 32) * (H_MID / 64));
        conv_w_tile(W2, w2o, H_MID, P_OUT, bx, by, e);
    }
}

// ---------------- grouped single-term fp16 mma.sync GEMM ----------------
// MT in {128, 64}; N tile 128; 256 threads; 2 CTAs/SM; 3-buffer single-sync
// pipeline; ALL addresses strength-reduced to pointer+offset adds.
template <int MT, bool SOFTSIGN>
__global__ __launch_bounds__(256, 2)
void mma_gemm(const __half* __restrict__ Aw,
              const __half* __restrict__ Bw,
              const float* __restrict__ bias,
              float* __restrict__ outF,
              __half* __restrict__ outH,
              int K, int Ntot)
{
    constexpr int MWARPS = MT / 32;
    constexpr int NWARPS = 8 / MWARPS;
    constexpr int WARP_N = 128 / NWARPS;       // 64 or 32
    constexpr int NP     = WARP_N / 16;        // 4 or 2
    constexpr int NT8    = WARP_N / 8;         // 8 or 4
    constexpr uint32_t OFF_B = MT * 128;
    constexpr uint32_t STAGE = MT * 128 + 16384;
    constexpr int A_SLOTS = MT * 8;
    constexpr int SLOTS   = A_SLOTS + 1024;
    constexpr int ITERS   = SLOTS / 256;       // 8 or 6
    constexpr int A_ITERS = A_SLOTS / 256;     // 4 or 2

    const int ntiles = (MT == 128) ? g_n128 : g_n64;
    if ((int)blockIdx.y >= ntiles) return;
    const int4 tt     = (MT == 128) ? g_t128[blockIdx.y] : g_t64[blockIdx.y];
    const int  e      = tt.x;
    const int  row0   = tt.y;
    const int  rowend = tt.z;

    extern __shared__ __align__(1024) char smem[];
    __shared__ int rm[MT];
    const uint32_t sb = smem_to_u32(smem);
    const int tid = threadIdx.x;
    const int wid = tid >> 5;
    const int lid = tid & 31;
    const int wm  = wid % MWARPS;
    const int wn  = wid / MWARPS;
    const int n0  = blockIdx.x * 128;

    if (tid < MT) {
        const int r = row0 + tid;
        rm[tid] = (r < rowend) ? g_rowmap[r] : -1;
    }
    __syncthreads();

    // ---- one-time cp.async pointer/offset setup ----
    const __half* srcp[ITERS];
    uint32_t dsto[ITERS];
#pragma unroll
    for (int it = 0; it < ITERS; it++) {
        int slot = it * 256 + tid;
        if (it < A_ITERS) {                      // A slots (compile-time split)
            int r = slot >> 3, c = slot & 7;
            int sr;
            if (SOFTSIGN) {
                sr = rm[r];
                if (sr < 0) sr = 0;              // padded row: load real data, discarded later
            } else {
                sr = row0 + r;                   // packed act rows (tail rows deterministic)
            }
            srcp[it] = Aw + (size_t)sr * K + c * 8;
            dsto[it] = SWZ128((uint32_t)(r * 128 + c * 16));
        } else {                                 // B slots
            int idx = slot - A_SLOTS;
            int r = idx >> 3, c = idx & 7;
            srcp[it] = Bw + ((size_t)e * Ntot + n0 + r) * K + c * 8;
            dsto[it] = OFF_B + SWZ128((uint32_t)(r * 128 + c * 16));
        }
    }
    // ---- one-time LDSM offset setup ----
    uint32_t offA[2][4], offB[NP][4];
#pragma unroll
    for (int kk = 0; kk < 4; kk++) {
        const uint32_t cb = (uint32_t)(kk * 32 + ((lid >> 4) << 4));
#pragma unroll
        for (int mt = 0; mt < 2; mt++)
            offA[mt][kk] =
                SWZ128((uint32_t)((wm * 32 + mt * 16 + (lid & 15)) * 128) + cb);
#pragma unroll
        for (int np = 0; np < NP; np++)
            offB[np][kk] = OFF_B +
                SWZ128((uint32_t)((wn * WARP_N + np * 16 + (lid & 15)) * 128) + cb);
    }

    const int nst = K >> 6;
    auto load_stage = [&](int s) {
        const uint32_t tb = sb + (uint32_t)(s % 3) * STAGE;
        const int koff = s << 6;
#pragma unroll
        for (int it = 0; it < ITERS; it++)
            cp16(tb + dsto[it], srcp[it] + koff);
        CP_COMMIT();
    };

    float acc[2][NT8][4];
#pragma unroll
    for (int mt = 0; mt < 2; mt++)
#pragma unroll
        for (int nt = 0; nt < NT8; nt++)
#pragma unroll
            for (int q = 0; q < 4; q++) acc[mt][nt][q] = 0.0f;

    load_stage(0);
    load_stage(1);

    for (int s = 0; s < nst; s++) {
        CP_WAIT1();
        __syncthreads();
        if (s + 2 < nst) load_stage(s + 2);
        else CP_COMMIT();

        const uint32_t base = sb + (uint32_t)(s % 3) * STAGE;
#pragma unroll
        for (int kk = 0; kk < 4; kk++) {
            uint32_t ah[2][4];
#pragma unroll
            for (int mt = 0; mt < 2; mt++)
                ldsm4(ah[mt], base + offA[mt][kk]);
#pragma unroll
            for (int np = 0; np < NP; np++) {
                uint32_t bh[4];
                ldsm4(bh, base + offB[np][kk]);
                const int nt0 = np * 2;
#pragma unroll
                for (int q = 0; q < 2; q++) {
                    mma16816(acc[0][nt0 + q], ah[0], bh[q], bh[2 + q]);
                    mma16816(acc[1][nt0 + q], ah[1], bh[q], bh[2 + q]);
                }
            }
        }
    }

    // ---------------- epilogue ----------------
    const int gq = lid >> 2;
    const int rq = lid & 3;
    float2 bv[NT8];
#pragma unroll
    for (int nt = 0; nt < NT8; nt++) {
        const int col = n0 + wn * WARP_N + nt * 8 + rq * 2;
        bv[nt] = *reinterpret_cast<const float2*>(bias + (size_t)e * Ntot + col);
    }

#pragma unroll
    for (int mt = 0; mt < 2; mt++) {
#pragma unroll
        for (int nt = 0; nt < NT8; nt++) {
            const int lr0 = wm * 32 + mt * 16 + gq;
            const int col = n0 + wn * WARP_N + nt * 8 + rq * 2;
            float c0 = acc[mt][nt][0] + bv[nt].x;
            float c1 = acc[mt][nt][1] + bv[nt].y;
            float c2 = acc[mt][nt][2] + bv[nt].x;
            float c3 = acc[mt][nt][3] + bv[nt].y;
            if (SOFTSIGN) {
                c0 = c0 / (1.0f + fabsf(c0));
                c1 = c1 / (1.0f + fabsf(c1));
                c2 = c2 / (1.0f + fabsf(c2));
                c3 = c3 / (1.0f + fabsf(c3));
                __half h0 = __float2half_rn(c0), h1 = __float2half_rn(c1);
                __half h2 = __float2half_rn(c2), h3 = __float2half_rn(c3);
                if (row0 + lr0 < rowend) {
                    size_t o0 = (size_t)(row0 + lr0) * Ntot + col;
                    *reinterpret_cast<__half2*>(outH + o0) = __half2(h0, h1);
                }
                if (row0 + lr0 + 8 < rowend) {
                    size_t o1 = (size_t)(row0 + lr0 + 8) * Ntot + col;
                    *reinterpret_cast<__half2*>(outH + o1) = __half2(h2, h3);
                }
            } else {
                const int d0 = rm[lr0];
                const int d1 = rm[lr0 + 8];
                if (d0 >= 0)
                    *reinterpret_cast<float2*>(outF + (size_t)d0 * Ntot + col) =
                        make_float2(c0, c1);
                if (d1 >= 0)
                    *reinterpret_cast<float2*>(outF + (size_t)d1 * Ntot + col) =
                        make_float2(c2, c3);
            }
        }
    }
}

// ---------------- host launcher ----------------
extern "C" void kernel_launch(void* const* d_in, const int* in_sizes, int n_in,
                              void* d_out, int out_size)
{
    const float* x   = (const float*)d_in[0];
    const int*   eid = (const int*)d_in[1];
    const float* W1  = (const float*)d_in[2];
    const float* b1  = (const float*)d_in[3];
    const float* W2  = (const float*)d_in[4];
    const float* b2  = (const float*)d_in[5];
    float* out = (float*)d_out;

    __half *xv, *w1, *w2, *av;
    cudaGetSymbolAddress((void**)&xv, g_x);
    cudaGetSymbolAddress((void**)&w1, g_w1);
    cudaGetSymbolAddress((void**)&w2, g_w2);
    cudaGetSymbolAddress((void**)&av, g_a);

    constexpr int SMEM1 = 3 * (128 * 128 + 16384);  // 98304
    constexpr int SMEM2 = 3 * (64 * 128 + 16384);   // 73728
    cudaFuncSetAttribute(mma_gemm<128, true>,
                         cudaFuncAttributeMaxDynamicSharedMemorySize, SMEM1);
    cudaFuncSetAttribute(mma_gemm<64, false>,
                         cudaFuncAttributeMaxDynamicSharedMemorySize, SMEM2);

    // 1) expert sort / tile tables / rowmap
    prep_kernel<<<1, 256>>>(eid);
    // 2) all conversions in one launch
    convert_all_kernel<<<XBLOCKS + W1BLOCKS + W2BLOCKS, 256>>>(x, W1, W2, xv, w1, w2);
    // 3) GEMM1: M128xN128 tiles
    mma_gemm<128, true><<<dim3(H_MID / 128, MAXT128), 256, SMEM1>>>(
        xv, w1, b1, nullptr, av, /*K=*/N_IN, /*Ntot=*/H_MID);
    // 4) GEMM2: M64xN128 tiles
    mma_gemm<64, false><<<dim3(P_OUT / 128, MAXT64), 256, SMEM2>>>(
        av, w2, b2, out, nullptr, /*K=*/H_MID, /*Ntot=*/P_OUT);
}